// round 9
// baseline (speedup 1.0000x reference)
#include <cuda_runtime.h>
#include <cstddef>
#include <cstdint>

// Problem constants
#define BB   64
#define NN   300
#define DDIM 512
#define HH   8
#define DHD  64
#define LLAY 6
#define DFF  2048
#define MM   (BB*NN)   // 19200 rows

// ---------------- scratch (no allocation allowed) ----------------
__device__ float g_x [MM*DDIM];
__device__ float g_k [MM*DDIM];
__device__ float g_o [MM*DDIM];
__device__ float g_z [MM*DDIM];
__device__ float g_h [(size_t)MM*DFF];
// pre-rounded (tf32-RNA) weights, [K][N] row-major, fp32 bit patterns
#define WK_OFF 0
#define WO_OFF (LLAY*DDIM*DDIM)
#define W1_OFF (2*LLAY*DDIM*DDIM)
#define W2_OFF (2*LLAY*DDIM*DDIM + LLAY*DDIM*DFF)
__device__ uint32_t g_wr[2*LLAY*DDIM*DDIM + 2*LLAY*DDIM*DFF];

__device__ __forceinline__ uint32_t f2tf(float x) {
    uint32_t r;
    asm("cvt.rna.tf32.f32 %0, %1;" : "=r"(r) : "f"(x));
    return r;
}

__device__ __forceinline__ void cp_async16(uint32_t smem_addr, const void* gptr) {
    asm volatile("cp.async.cg.shared.global [%0], [%1], 16;\n"
                 :: "r"(smem_addr), "l"(gptr));
}

#define MMA_TF32(acc, a0,a1,a2,a3, b0,b1)                                   \
    asm volatile(                                                           \
        "mma.sync.aligned.m16n8k8.row.col.f32.tf32.tf32.f32 "               \
        "{%0,%1,%2,%3}, {%4,%5,%6,%7}, {%8,%9}, {%0,%1,%2,%3};"             \
        : "+f"(acc[0]), "+f"(acc[1]), "+f"(acc[2]), "+f"(acc[3])            \
        : "r"(a0), "r"(a1), "r"(a2), "r"(a3), "r"(b0), "r"(b1))

#define LDSM_X4(r0,r1,r2,r3, addr)                                          \
    asm volatile(                                                           \
        "ldmatrix.sync.aligned.m8n8.x4.shared.b16 {%0,%1,%2,%3}, [%4];"     \
        : "=r"(r0), "=r"(r1), "=r"(r2), "=r"(r3) : "r"(addr))

// ---------------- embed: x = emb[tok] + pos ----------------
__global__ void embed_kernel(const int* __restrict__ tok,
                             const float* __restrict__ emb,
                             const float* __restrict__ pos,
                             float* __restrict__ x)
{
    int gid = blockIdx.x * blockDim.x + threadIdx.x;
    int row = gid >> 7;
    int c   = gid & 127;
    int t   = tok[row];
    int n   = row % NN;
    float4 e = ((const float4*)emb)[(size_t)t * 128 + c];
    float4 p = ((const float4*)pos)[(size_t)n * 128 + c];
    ((float4*)x)[gid] = make_float4(e.x + p.x, e.y + p.y, e.z + p.z, e.w + p.w);
}

// ---------------- weight pre-round (RNA tf32), plain copy [K][N] ----------------
__global__ void round_copy_kernel(const float* __restrict__ in,
                                  uint32_t* __restrict__ out, int n4)
{
    int idx = blockIdx.x * blockDim.x + threadIdx.x;
    if (idx >= n4) return;
    float4 v = ((const float4*)in)[idx];
    uint4 r;
    r.x = f2tf(v.x); r.y = f2tf(v.y); r.z = f2tf(v.z); r.w = f2tf(v.w);
    ((uint4*)out)[idx] = r;
}

// ---------------- Wk pre-round + pack (H,D,DH) -> [K=D][N=H*DH], all layers ----------------
__global__ void round_pack_wk_kernel(const float* __restrict__ wk,
                                     uint32_t* __restrict__ out)
{
    int idx = blockIdx.x * blockDim.x + threadIdx.x;   // over LLAY*DDIM*DDIM
    int e = idx & (DDIM * DDIM - 1);
    int l = idx >> 18;
    int d = e >> 9;
    int c = e & 511;
    float v = wk[(size_t)l * (HH * DDIM * DHD) +
                 (size_t)(c >> 6) * (DDIM * DHD) + (size_t)d * DHD + (c & 63)];
    out[idx] = f2tf(v);
}

// ---------------- tf32 tensor-core GEMM, BM=256, BN=128, BK=32, 512 threads ----------------
// A [M][K] fp32 (cvt.rna on fragments). B [K][N] pre-rounded bits (raw loads).
#define BKK     32
#define ASTRIDE 36            // 256 rows; LDSM row banks 4i mod 32 distinct
#define BSTRIDE 136           // 32 rows; scalar B banks 8*tig+g distinct
#define A_STAGE (256*ASTRIDE) // floats
#define B_STAGE (BKK*BSTRIDE)
#define GEMM_SMEM ((2*(A_STAGE + B_STAGE)) * 4)

__global__ __launch_bounds__(512, 1)
void mma_gemm_kernel(const float* __restrict__ A, const uint32_t* __restrict__ Bm,
                     float* __restrict__ C, int Mdim, int Ndim, int Kdim,
                     const float* __restrict__ bias, int relu)
{
    extern __shared__ float dsm[];
    float*    Asm = dsm;                       // 2 stages
    uint32_t* Bsm = (uint32_t*)(dsm + 2 * A_STAGE);

    const int tid  = threadIdx.x;
    const int lane = tid & 31;
    const int w    = tid >> 5;            // 0..15
    const int g    = lane >> 2;
    const int tig  = lane & 3;

    const int warp_m = (w & 3) * 64;      // 0,64,128,192
    const int warp_n = (w >> 2) * 32;     // 0,32,64,96

    const int cRow = blockIdx.y * 256;
    const int cCol = blockIdx.x * 128;

    // A copy: 2048 16B-chunks (256 rows x 8), 4 per thread
    const int ar0 = tid >> 3;             // rows tid>>3 + {0,64,128,192}
    const int ac0 = (tid & 7) * 4;
    // B copy: 1024 16B-chunks (32 rows x 32), 2 per thread
    const int br0 = tid >> 5;             // 0..15 (+16)
    const int bc0 = (tid & 31) * 4;

    const float*    Ag = A  + (size_t)cRow * Kdim;
    const uint32_t* Bg = Bm + cCol;

    const uint32_t as_base = (uint32_t)__cvta_generic_to_shared(Asm);
    const uint32_t a_ld_off =
        ((uint32_t)(warp_m + (lane & 15)) * ASTRIDE + ((lane >> 4) << 2)) * 4;

    float acc[4][4][4];
    #pragma unroll
    for (int mi = 0; mi < 4; mi++)
        #pragma unroll
        for (int ni = 0; ni < 4; ni++)
            #pragma unroll
            for (int r = 0; r < 4; r++) acc[mi][ni][r] = 0.f;

    const int ktiles = Kdim >> 5;

    // prologue: tile 0 -> buf 0
    {
        #pragma unroll
        for (int i = 0; i < 4; i++) {
            int arow = ar0 + i * 64;
            cp_async16((uint32_t)__cvta_generic_to_shared(Asm + arow * ASTRIDE + ac0),
                       Ag + (size_t)arow * Kdim + ac0);
        }
        #pragma unroll
        for (int i = 0; i < 2; i++) {
            int brow = br0 + i * 16;
            cp_async16((uint32_t)__cvta_generic_to_shared(Bsm + brow * BSTRIDE + bc0),
                       Bg + (size_t)brow * Ndim + bc0);
        }
        asm volatile("cp.async.commit_group;\n");
    }

    for (int t = 0; t < ktiles; t++) {
        if (t + 1 < ktiles) {
            const int nb = (t + 1) & 1;
            const int k0 = (t + 1) << 5;
            float*    Asw = Asm + nb * A_STAGE;
            uint32_t* Bsw = Bsm + nb * B_STAGE;
            #pragma unroll
            for (int i = 0; i < 4; i++) {
                int arow = ar0 + i * 64;
                cp_async16((uint32_t)__cvta_generic_to_shared(Asw + arow * ASTRIDE + ac0),
                           Ag + (size_t)arow * Kdim + k0 + ac0);
            }
            #pragma unroll
            for (int i = 0; i < 2; i++) {
                int brow = br0 + i * 16;
                cp_async16((uint32_t)__cvta_generic_to_shared(Bsw + brow * BSTRIDE + bc0),
                           Bg + (size_t)(k0 + brow) * Ndim + bc0);
            }
            asm volatile("cp.async.commit_group;\n");
            asm volatile("cp.async.wait_group 1;\n");
        } else {
            asm volatile("cp.async.wait_group 0;\n");
        }
        __syncthreads();

        const int buf = t & 1;
        const uint32_t a_stage = as_base + (uint32_t)(buf * A_STAGE) * 4 + a_ld_off;
        const uint32_t* bstage = Bsm + buf * B_STAGE;
        #pragma unroll
        for (int s = 0; s < 4; s++) {
            const int k8 = s * 8;
            uint32_t af[4][4];
            #pragma unroll
            for (int mi = 0; mi < 4; mi++) {
                uint32_t r0, r1, r2, r3;
                LDSM_X4(r0, r1, r2, r3,
                        a_stage + (uint32_t)(mi * 16 * ASTRIDE + k8) * 4);
                af[mi][0] = f2tf(__uint_as_float(r0));
                af[mi][1] = f2tf(__uint_as_float(r1));
                af[mi][2] = f2tf(__uint_as_float(r2));
                af[mi][3] = f2tf(__uint_as_float(r3));
            }
            uint32_t bf[4][2];
            #pragma unroll
            for (int ni = 0; ni < 4; ni++) {
                int cb = warp_n + ni * 8 + g;
                bf[ni][0] = bstage[(k8 + tig    ) * BSTRIDE + cb];
                bf[ni][1] = bstage[(k8 + tig + 4) * BSTRIDE + cb];
            }
            #pragma unroll
            for (int mi = 0; mi < 4; mi++)
                #pragma unroll
                for (int ni = 0; ni < 4; ni++)
                    MMA_TF32(acc[mi][ni], af[mi][0], af[mi][1], af[mi][2], af[mi][3],
                             bf[ni][0], bf[ni][1]);
        }
        __syncthreads();
    }

    #pragma unroll
    for (int mi = 0; mi < 4; mi++) {
        int row0 = cRow + warp_m + mi * 16 + g;
        #pragma unroll
        for (int ni = 0; ni < 4; ni++) {
            int col = cCol + warp_n + ni * 8 + 2 * tig;
            float2 v0 = make_float2(acc[mi][ni][0], acc[mi][ni][1]);
            float2 v1 = make_float2(acc[mi][ni][2], acc[mi][ni][3]);
            if (bias) {
                float2 bb = *(const float2*)(bias + col);
                v0.x += bb.x; v0.y += bb.y;
                v1.x += bb.x; v1.y += bb.y;
            }
            if (relu) {
                v0.x = fmaxf(v0.x, 0.f); v0.y = fmaxf(v0.y, 0.f);
                v1.x = fmaxf(v1.x, 0.f); v1.y = fmaxf(v1.y, 0.f);
            }
            *(float2*)(C + (size_t)row0       * Ndim + col) = v0;
            *(float2*)(C + (size_t)(row0 + 8) * Ndim + col) = v1;
        }
    }
}

// ---------------- tensor-core attention (512 threads, ldmatrix, RNA at load) ----------------
#define KPAD   320
#define KLD    68
#define SLD    324
#define MQ     64
#define ATTN_SMEM ((KPAD*KLD + MQ*SLD) * 4)

__global__ __launch_bounds__(512, 1)
void attn_mma_kernel(const float* __restrict__ k, float* __restrict__ o)
{
    extern __shared__ uint32_t smu[];
    uint32_t* Ks  = smu;                    // KPAD*KLD tf32 bits (RNA at load)
    uint32_t* SsB = smu + KPAD * KLD;       // MQ*SLD (bits view)
    float*    Ssf = (float*)SsB;

    const int bh = blockIdx.x;
    const int b  = bh / HH, h = bh % HH;
    const float* kbase = k + (size_t)b * NN * DDIM + h * DHD;

    const int tid  = threadIdx.x;
    const int lane = tid & 31;
    const int w    = tid >> 5;      // 0..15
    const int g    = lane >> 2;
    const int tig  = lane & 3;

    const uint32_t ks_addr = (uint32_t)__cvta_generic_to_shared(Ks);
    const uint32_t ss_addr = (uint32_t)__cvta_generic_to_shared(SsB);

    for (int i = tid; i < KPAD * DHD; i += 512) {
        int m = i >> 6, e = i & 63;
        float v = (m < NN) ? kbase[(size_t)m * DDIM + e] : 0.f;
        Ks[m * KLD + e] = f2tf(v);
    }
    __syncthreads();

    const float scale = 0.04419417382415922f;   // 1/sqrt(512)
    const int mi  = w & 3;
    const int qtr = w >> 2;

    const uint32_t a_row  = (uint32_t)(mi * 16 + (lane & 15));
    const uint32_t a_coff = (uint32_t)((lane >> 4) << 2);
    const uint32_t b_row  = (uint32_t)(qtr * 80 + (lane & 7) + ((lane & 16) >> 1));
    const uint32_t b_coff = (uint32_t)((lane & 8) >> 1);

    for (int it = 0; it < 5; it++) {
        const int q0 = it * MQ;

        // ---- S = Q K^T ----
        {
            float acc[10][4];
            #pragma unroll
            for (int ni = 0; ni < 10; ni++)
                #pragma unroll
                for (int r = 0; r < 4; r++) acc[ni][r] = 0.f;

            const uint32_t a_base = ks_addr + ((q0 + a_row) * KLD + a_coff) * 4;
            const uint32_t b_base = ks_addr + (b_row * KLD + b_coff) * 4;

            #pragma unroll
            for (int ks = 0; ks < 8; ks++) {
                const uint32_t kc4 = (uint32_t)(ks * 8) * 4;
                uint32_t a0, a1, a2, a3;
                LDSM_X4(a0, a1, a2, a3, a_base + kc4);
                #pragma unroll
                for (int p = 0; p < 5; p++) {
                    uint32_t b0, b1, b2, b3;
                    LDSM_X4(b0, b1, b2, b3,
                            b_base + (uint32_t)(p * 16 * KLD) * 4 + kc4);
                    MMA_TF32(acc[2*p    ], a0, a1, a2, a3, b0, b1);
                    MMA_TF32(acc[2*p + 1], a0, a1, a2, a3, b2, b3);
                }
            }
            const int row0 = mi * 16 + g;
            #pragma unroll
            for (int ni = 0; ni < 10; ni++) {
                int col = qtr * 80 + ni * 8 + 2 * tig;
                Ssf[row0 * SLD + col    ] = (col     < NN) ? acc[ni][0] * scale : -1e30f;
                Ssf[row0 * SLD + col + 1] = (col + 1 < NN) ? acc[ni][1] * scale : -1e30f;
                Ssf[(row0+8) * SLD + col    ] = (col     < NN) ? acc[ni][2] * scale : -1e30f;
                Ssf[(row0+8) * SLD + col + 1] = (col + 1 < NN) ? acc[ni][3] * scale : -1e30f;
            }
        }
        __syncthreads();

        // ---- softmax: warp w -> rows [4w, 4w+4) ----
        #pragma unroll
        for (int r = 0; r < 4; r++) {
            const int row = w * 4 + r;
            float* srow = Ssf + row * SLD;
            float v[10];
            float mx = -1e30f;
            #pragma unroll
            for (int j = 0; j < 10; j++) {
                float s = srow[lane + 32 * j];
                v[j] = s;
                mx = fmaxf(mx, s);
            }
            #pragma unroll
            for (int off = 16; off; off >>= 1)
                mx = fmaxf(mx, __shfl_xor_sync(0xffffffffu, mx, off));
            float sum = 0.f;
            #pragma unroll
            for (int j = 0; j < 10; j++) {
                float ev = __expf(v[j] - mx);
                v[j] = ev;
                sum += ev;
            }
            #pragma unroll
            for (int off = 16; off; off >>= 1)
                sum += __shfl_xor_sync(0xffffffffu, sum, off);
            float inv = 1.f / sum;
            #pragma unroll
            for (int j = 0; j < 10; j++)
                SsB[row * SLD + lane + 32 * j] = f2tf(v[j] * inv);
        }
        __syncthreads();

        // ---- O = P K : 38 k-steps (keys 304..319 have exactly-zero prob) ----
        {
            float oacc[2][4];
            #pragma unroll
            for (int ni = 0; ni < 2; ni++)
                #pragma unroll
                for (int r = 0; r < 4; r++) oacc[ni][r] = 0.f;

            const uint32_t pa_base = ss_addr + (a_row * SLD + a_coff) * 4;
            const int ch0 = qtr * 16 + g;

            #pragma unroll 2
            for (int ks = 0; ks < 38; ks++) {
                const int kc = ks * 8;
                uint32_t a0, a1, a2, a3;
                LDSM_X4(a0, a1, a2, a3, pa_base + (uint32_t)kc * 4);
                uint32_t b00 = Ks[(kc + tig    ) * KLD + ch0    ];
                uint32_t b01 = Ks[(kc + tig + 4) * KLD + ch0    ];
                uint32_t b10 = Ks[(kc + tig    ) * KLD + ch0 + 8];
                uint32_t b11 = Ks[(kc + tig + 4) * KLD + ch0 + 8];
                MMA_TF32(oacc[0], a0, a1, a2, a3, b00, b01);
                MMA_TF32(oacc[1], a0, a1, a2, a3, b10, b11);
            }
            const int q = q0 + mi * 16 + g;
            float* ob = o + (size_t)b * NN * DDIM + h * DHD;
            #pragma unroll
            for (int ni = 0; ni < 2; ni++) {
                int ch = qtr * 16 + ni * 8 + 2 * tig;
                if (q < NN)
                    *(float2*)(ob + (size_t)q * DDIM + ch) =
                        make_float2(oacc[ni][0], oacc[ni][1]);
                if (q + 8 < NN)
                    *(float2*)(ob + (size_t)(q + 8) * DDIM + ch) =
                        make_float2(oacc[ni][2], oacc[ni][3]);
            }
        }
        __syncthreads();
    }
}

// ---------------- residual + LayerNorm ----------------
__global__ __launch_bounds__(256)
void ln_kernel(const float* __restrict__ a, const float* __restrict__ b,
               const float* __restrict__ gamma, const float* __restrict__ beta,
               float* __restrict__ out)
{
    int w    = threadIdx.x >> 5;
    int lane = threadIdx.x & 31;
    int row  = blockIdx.x * 8 + w;

    const float4* a4 = (const float4*)(a + (size_t)row * DDIM);
    const float4* b4 = (const float4*)(b + (size_t)row * DDIM);
    float4 v[4];
    float s1 = 0.f, s2 = 0.f;
    #pragma unroll
    for (int j = 0; j < 4; j++) {
        float4 av = a4[j * 32 + lane];
        float4 bv = b4[j * 32 + lane];
        float4 t = make_float4(av.x + bv.x, av.y + bv.y, av.z + bv.z, av.w + bv.w);
        v[j] = t;
        s1 += t.x + t.y + t.z + t.w;
        s2 += t.x * t.x + t.y * t.y + t.z * t.z + t.w * t.w;
    }
    #pragma unroll
    for (int off = 16; off; off >>= 1) {
        s1 += __shfl_xor_sync(0xffffffffu, s1, off);
        s2 += __shfl_xor_sync(0xffffffffu, s2, off);
    }
    float mean = s1 * (1.f / DDIM);
    float var  = s2 * (1.f / DDIM) - mean * mean;
    float rs   = rsqrtf(var + 1e-5f);

    const float4* g4  = (const float4*)gamma;
    const float4* be4 = (const float4*)beta;
    float4* o4 = (float4*)(out + (size_t)row * DDIM);
    #pragma unroll
    for (int j = 0; j < 4; j++) {
        float4 g = g4[j * 32 + lane];
        float4 be = be4[j * 32 + lane];
        float4 t = v[j];
        float4 r;
        r.x = (t.x - mean) * rs * g.x + be.x;
        r.y = (t.y - mean) * rs * g.y + be.y;
        r.z = (t.z - mean) * rs * g.z + be.z;
        r.w = (t.w - mean) * rs * g.w + be.w;
        o4[j * 32 + lane] = r;
    }
}

// ---------------- launcher ----------------
extern "C" void kernel_launch(void* const* d_in, const int* in_sizes, int n_in,
                              void* d_out, int out_size)
{
    const int*   tokens = (const int*)  d_in[0];
    const float* emb    = (const float*)d_in[1];
    const float* pos    = (const float*)d_in[2];
    const float* Wk     = (const float*)d_in[3];
    const float* Wo     = (const float*)d_in[4];
    const float* W1     = (const float*)d_in[5];
    const float* b1     = (const float*)d_in[6];
    const float* W2     = (const float*)d_in[7];
    const float* b2     = (const float*)d_in[8];
    const float* gamma  = (const float*)d_in[9];
    const float* beta   = (const float*)d_in[10];

    float *x, *k, *o, *z, *h;
    uint32_t* wr;
    cudaGetSymbolAddress((void**)&x,  g_x);
    cudaGetSymbolAddress((void**)&k,  g_k);
    cudaGetSymbolAddress((void**)&o,  g_o);
    cudaGetSymbolAddress((void**)&z,  g_z);
    cudaGetSymbolAddress((void**)&h,  g_h);
    cudaGetSymbolAddress((void**)&wr, g_wr);

    cudaFuncSetAttribute(attn_mma_kernel,
                         cudaFuncAttributeMaxDynamicSharedMemorySize, ATTN_SMEM);
    cudaFuncSetAttribute(mma_gemm_kernel,
                         cudaFuncAttributeMaxDynamicSharedMemorySize, GEMM_SMEM);

    // weight pre-round (all layers, once per launch)
    round_pack_wk_kernel<<<(LLAY * DDIM * DDIM) / 256, 256>>>(Wk, wr + WK_OFF);
    round_copy_kernel<<<(LLAY * DDIM * DDIM / 4 + 255) / 256, 256>>>(
        Wo, wr + WO_OFF, LLAY * DDIM * DDIM / 4);
    round_copy_kernel<<<(LLAY * DDIM * DFF / 4 + 255) / 256, 256>>>(
        W1, wr + W1_OFF, LLAY * DDIM * DFF / 4);
    round_copy_kernel<<<(LLAY * DDIM * DFF / 4 + 255) / 256, 256>>>(
        W2, wr + W2_OFF, LLAY * DDIM * DFF / 4);

    embed_kernel<<<(MM * 128) / 256, 256>>>(tokens, emb, pos, x);

    for (int l = 0; l < LLAY; l++) {
        mma_gemm_kernel<<<dim3(DDIM / 128, MM / 256), 512, GEMM_SMEM>>>(
            x, wr + WK_OFF + (size_t)l * DDIM * DDIM, k, MM, DDIM, DDIM,
            nullptr, 0);

        attn_mma_kernel<<<BB * HH, 512, ATTN_SMEM>>>(k, o);

        mma_gemm_kernel<<<dim3(DDIM / 128, MM / 256), 512, GEMM_SMEM>>>(
            o, wr + WO_OFF + (size_t)l * DDIM * DDIM, h, MM, DDIM, DDIM,
            nullptr, 0);

        ln_kernel<<<MM / 8, 256>>>(h, x, gamma + (size_t)l * DDIM,
                                   beta + (size_t)l * DDIM, z);

        mma_gemm_kernel<<<dim3(DFF / 128, MM / 256), 512, GEMM_SMEM>>>(
            z, wr + W1_OFF + (size_t)l * DDIM * DFF, h, MM, DFF, DDIM,
            b1 + (size_t)l * DFF, 1);

        mma_gemm_kernel<<<dim3(DDIM / 128, MM / 256), 512, GEMM_SMEM>>>(
            h, wr + W2_OFF + (size_t)l * DFF * DDIM, k, MM, DDIM, DFF,
            b2 + (size_t)l * DDIM, 0);

        float* dst = (l == LLAY - 1) ? (float*)d_out : x;
        ln_kernel<<<MM / 8, 256>>>(k, z, gamma + (size_t)l * DDIM,
                                   beta + (size_t)l * DDIM, dst);
    }
}

// round 10
// speedup vs baseline: 1.0295x; 1.0295x over previous
#include <cuda_runtime.h>
#include <cstddef>
#include <cstdint>

// Problem constants
#define BB   64
#define NN   300
#define DDIM 512
#define HH   8
#define DHD  64
#define LLAY 6
#define DFF  2048
#define MM   (BB*NN)   // 19200 rows

// ---------------- scratch (no allocation allowed) ----------------
__device__ float g_x [MM*DDIM];
__device__ float g_k [MM*DDIM];
__device__ float g_o [MM*DDIM];
__device__ float g_z [MM*DDIM];
__device__ float g_h [(size_t)MM*DFF];
// pre-rounded (tf32-RNA) weights, [K][N] row-major, fp32 bit patterns
#define WK_OFF 0
#define WO_OFF (LLAY*DDIM*DDIM)
#define W1_OFF (2*LLAY*DDIM*DDIM)
#define W2_OFF (2*LLAY*DDIM*DDIM + LLAY*DDIM*DFF)
__device__ uint32_t g_wr[2*LLAY*DDIM*DDIM + 2*LLAY*DDIM*DFF];

__device__ __forceinline__ uint32_t f2tf(float x) {
    uint32_t r;
    asm("cvt.rna.tf32.f32 %0, %1;" : "=r"(r) : "f"(x));
    return r;
}

__device__ __forceinline__ void cp_async16(uint32_t smem_addr, const void* gptr) {
    asm volatile("cp.async.cg.shared.global [%0], [%1], 16;\n"
                 :: "r"(smem_addr), "l"(gptr));
}

#define MMA_TF32(acc, a0,a1,a2,a3, b0,b1)                                   \
    asm volatile(                                                           \
        "mma.sync.aligned.m16n8k8.row.col.f32.tf32.tf32.f32 "               \
        "{%0,%1,%2,%3}, {%4,%5,%6,%7}, {%8,%9}, {%0,%1,%2,%3};"             \
        : "+f"(acc[0]), "+f"(acc[1]), "+f"(acc[2]), "+f"(acc[3])            \
        : "r"(a0), "r"(a1), "r"(a2), "r"(a3), "r"(b0), "r"(b1))

#define LDSM_X4(r0,r1,r2,r3, addr)                                          \
    asm volatile(                                                           \
        "ldmatrix.sync.aligned.m8n8.x4.shared.b16 {%0,%1,%2,%3}, [%4];"     \
        : "=r"(r0), "=r"(r1), "=r"(r2), "=r"(r3) : "r"(addr))

// ---------------- embed: x = emb[tok] + pos ----------------
__global__ void embed_kernel(const int* __restrict__ tok,
                             const float* __restrict__ emb,
                             const float* __restrict__ pos,
                             float* __restrict__ x)
{
    int gid = blockIdx.x * blockDim.x + threadIdx.x;
    int row = gid >> 7;
    int c   = gid & 127;
    int t   = tok[row];
    int n   = row % NN;
    float4 e = ((const float4*)emb)[(size_t)t * 128 + c];
    float4 p = ((const float4*)pos)[(size_t)n * 128 + c];
    ((float4*)x)[gid] = make_float4(e.x + p.x, e.y + p.y, e.z + p.z, e.w + p.w);
}

// ---------------- weight pre-round (RNA tf32), plain copy [K][N] ----------------
__global__ void round_copy_kernel(const float* __restrict__ in,
                                  uint32_t* __restrict__ out, int n4)
{
    int idx = blockIdx.x * blockDim.x + threadIdx.x;
    if (idx >= n4) return;
    float4 v = ((const float4*)in)[idx];
    uint4 r;
    r.x = f2tf(v.x); r.y = f2tf(v.y); r.z = f2tf(v.z); r.w = f2tf(v.w);
    ((uint4*)out)[idx] = r;
}

// ---------------- Wk pre-round + pack (H,D,DH) -> [K=D][N=H*DH], all layers ----------------
__global__ void round_pack_wk_kernel(const float* __restrict__ wk,
                                     uint32_t* __restrict__ out)
{
    int idx = blockIdx.x * blockDim.x + threadIdx.x;   // over LLAY*DDIM*DDIM
    int e = idx & (DDIM * DDIM - 1);
    int l = idx >> 18;
    int d = e >> 9;
    int c = e & 511;
    float v = wk[(size_t)l * (HH * DDIM * DHD) +
                 (size_t)(c >> 6) * (DDIM * DHD) + (size_t)d * DHD + (c & 63)];
    out[idx] = f2tf(v);
}

// ---------------- tf32 tensor-core GEMM, BM=128, BK=32, 3-stage, 1 sync/ktile ----------------
// A [M][K] fp32 (cvt.rna on fragments). B [K][N] pre-rounded bits (raw loads).
#define BKK     32
#define ASTRIDE 36            // 128 rows; LDSM row banks 4i mod 32 distinct
#define BSTRIDE 136           // 32 rows; scalar B banks 8*tig+g distinct
#define A_STAGE (128*ASTRIDE) // floats
#define B_STAGE (BKK*BSTRIDE)
#define NSTAGE  3
#define GEMM_SMEM ((NSTAGE*(A_STAGE + B_STAGE)) * 4)

__global__ __launch_bounds__(256)
void mma_gemm_kernel(const float* __restrict__ A, const uint32_t* __restrict__ Bm,
                     float* __restrict__ C, int Mdim, int Ndim, int Kdim,
                     const float* __restrict__ bias, int relu)
{
    extern __shared__ float dsm[];
    float*    Asm = dsm;                           // NSTAGE stages
    uint32_t* Bsm = (uint32_t*)(dsm + NSTAGE * A_STAGE);

    const int tid  = threadIdx.x;
    const int lane = tid & 31;
    const int w    = tid >> 5;
    const int g    = lane >> 2;
    const int tig  = lane & 3;

    const int warp_m = (w & 1) * 64;
    const int warp_n = (w >> 1) * 32;

    const int cRow = blockIdx.y * 128;
    const int cCol = blockIdx.x * 128;

    // A copy: 1024 16B-chunks (128 rows x 8), 4 per thread
    const int ar0 = tid >> 3;
    const int ac0 = (tid & 7) * 4;
    // B copy: 1024 16B-chunks (32 rows x 32), 4 per thread
    const int br0 = tid >> 5;
    const int bc0 = (tid & 31) * 4;

    const float*    Ag = A  + (size_t)cRow * Kdim;
    const uint32_t* Bg = Bm + cCol;

    const uint32_t as_base = (uint32_t)__cvta_generic_to_shared(Asm);
    const uint32_t a_ld_off =
        ((uint32_t)(warp_m + (lane & 15)) * ASTRIDE + ((lane >> 4) << 2)) * 4;

    float acc[4][4][4];
    #pragma unroll
    for (int mi = 0; mi < 4; mi++)
        #pragma unroll
        for (int ni = 0; ni < 4; ni++)
            #pragma unroll
            for (int r = 0; r < 4; r++) acc[mi][ni][r] = 0.f;

    const int ktiles = Kdim >> 5;

    // prologue: tiles 0,1 -> stages 0,1 (2 committed groups)
    #pragma unroll
    for (int s = 0; s < 2; s++) {
        float*    Asw = Asm + s * A_STAGE;
        uint32_t* Bsw = Bsm + s * B_STAGE;
        const int k0 = s << 5;
        #pragma unroll
        for (int i = 0; i < 4; i++) {
            int arow = ar0 + i * 32;
            cp_async16((uint32_t)__cvta_generic_to_shared(Asw + arow * ASTRIDE + ac0),
                       Ag + (size_t)arow * Kdim + k0 + ac0);
            int brow = br0 + i * 8;
            cp_async16((uint32_t)__cvta_generic_to_shared(Bsw + brow * BSTRIDE + bc0),
                       Bg + (size_t)(k0 + brow) * Ndim + bc0);
        }
        asm volatile("cp.async.commit_group;\n");
    }

    for (int t = 0; t < ktiles; t++) {
        // wait for tile t (groups complete in order)
        if (t + 1 < ktiles) {
            asm volatile("cp.async.wait_group 1;\n");
        } else {
            asm volatile("cp.async.wait_group 0;\n");
        }
        __syncthreads();   // single barrier per ktile

        const int buf = t % NSTAGE;
        const uint32_t a_stage = as_base + (uint32_t)(buf * A_STAGE) * 4 + a_ld_off;
        const uint32_t* bstage = Bsm + buf * B_STAGE;
        #pragma unroll
        for (int s = 0; s < 4; s++) {
            const int k8 = s * 8;
            uint32_t af[4][4];
            #pragma unroll
            for (int mi = 0; mi < 4; mi++) {
                uint32_t r0, r1, r2, r3;
                LDSM_X4(r0, r1, r2, r3,
                        a_stage + (uint32_t)(mi * 16 * ASTRIDE + k8) * 4);
                af[mi][0] = f2tf(__uint_as_float(r0));
                af[mi][1] = f2tf(__uint_as_float(r1));
                af[mi][2] = f2tf(__uint_as_float(r2));
                af[mi][3] = f2tf(__uint_as_float(r3));
            }
            uint32_t bf[4][2];
            #pragma unroll
            for (int ni = 0; ni < 4; ni++) {
                int cb = warp_n + ni * 8 + g;
                bf[ni][0] = bstage[(k8 + tig    ) * BSTRIDE + cb];
                bf[ni][1] = bstage[(k8 + tig + 4) * BSTRIDE + cb];
            }
            #pragma unroll
            for (int mi = 0; mi < 4; mi++)
                #pragma unroll
                for (int ni = 0; ni < 4; ni++)
                    MMA_TF32(acc[mi][ni], af[mi][0], af[mi][1], af[mi][2], af[mi][3],
                             bf[ni][0], bf[ni][1]);
        }

        // prefetch tile t+2 into stage (t+2)%3 — its last readers were at
        // iteration t-1, and every warp here has passed sync(t), which is
        // only reachable after all warps finished compute(t-1).
        if (t + 2 < ktiles) {
            const int sb = (t + 2) % NSTAGE;
            const int k0 = (t + 2) << 5;
            float*    Asw = Asm + sb * A_STAGE;
            uint32_t* Bsw = Bsm + sb * B_STAGE;
            #pragma unroll
            for (int i = 0; i < 4; i++) {
                int arow = ar0 + i * 32;
                cp_async16((uint32_t)__cvta_generic_to_shared(Asw + arow * ASTRIDE + ac0),
                           Ag + (size_t)arow * Kdim + k0 + ac0);
                int brow = br0 + i * 8;
                cp_async16((uint32_t)__cvta_generic_to_shared(Bsw + brow * BSTRIDE + bc0),
                           Bg + (size_t)(k0 + brow) * Ndim + bc0);
            }
            asm volatile("cp.async.commit_group;\n");
        }
    }

    #pragma unroll
    for (int mi = 0; mi < 4; mi++) {
        int row0 = cRow + warp_m + mi * 16 + g;
        #pragma unroll
        for (int ni = 0; ni < 4; ni++) {
            int col = cCol + warp_n + ni * 8 + 2 * tig;
            float2 v0 = make_float2(acc[mi][ni][0], acc[mi][ni][1]);
            float2 v1 = make_float2(acc[mi][ni][2], acc[mi][ni][3]);
            if (bias) {
                float2 bb = *(const float2*)(bias + col);
                v0.x += bb.x; v0.y += bb.y;
                v1.x += bb.x; v1.y += bb.y;
            }
            if (relu) {
                v0.x = fmaxf(v0.x, 0.f); v0.y = fmaxf(v0.y, 0.f);
                v1.x = fmaxf(v1.x, 0.f); v1.y = fmaxf(v1.y, 0.f);
            }
            *(float2*)(C + (size_t)row0       * Ndim + col) = v0;
            *(float2*)(C + (size_t)(row0 + 8) * Ndim + col) = v1;
        }
    }
}

// ---------------- tensor-core attention (512 threads, ldmatrix, RNA at load) ----------------
#define KPAD   320
#define KLD    68
#define SLD    324
#define MQ     64
#define ATTN_SMEM ((KPAD*KLD + MQ*SLD) * 4)

__global__ __launch_bounds__(512, 1)
void attn_mma_kernel(const float* __restrict__ k, float* __restrict__ o)
{
    extern __shared__ uint32_t smu[];
    uint32_t* Ks  = smu;                    // KPAD*KLD tf32 bits (RNA at load)
    uint32_t* SsB = smu + KPAD * KLD;       // MQ*SLD (bits view)
    float*    Ssf = (float*)SsB;

    const int bh = blockIdx.x;
    const int b  = bh / HH, h = bh % HH;
    const float* kbase = k + (size_t)b * NN * DDIM + h * DHD;

    const int tid  = threadIdx.x;
    const int lane = tid & 31;
    const int w    = tid >> 5;      // 0..15
    const int g    = lane >> 2;
    const int tig  = lane & 3;

    const uint32_t ks_addr = (uint32_t)__cvta_generic_to_shared(Ks);
    const uint32_t ss_addr = (uint32_t)__cvta_generic_to_shared(SsB);

    for (int i = tid; i < KPAD * DHD; i += 512) {
        int m = i >> 6, e = i & 63;
        float v = (m < NN) ? kbase[(size_t)m * DDIM + e] : 0.f;
        Ks[m * KLD + e] = f2tf(v);
    }
    __syncthreads();

    const float scale = 0.04419417382415922f;   // 1/sqrt(512)
    const int mi  = w & 3;
    const int qtr = w >> 2;

    const uint32_t a_row  = (uint32_t)(mi * 16 + (lane & 15));
    const uint32_t a_coff = (uint32_t)((lane >> 4) << 2);
    const uint32_t b_row  = (uint32_t)(qtr * 80 + (lane & 7) + ((lane & 16) >> 1));
    const uint32_t b_coff = (uint32_t)((lane & 8) >> 1);

    for (int it = 0; it < 5; it++) {
        const int q0 = it * MQ;

        // ---- S = Q K^T ----
        {
            float acc[10][4];
            #pragma unroll
            for (int ni = 0; ni < 10; ni++)
                #pragma unroll
                for (int r = 0; r < 4; r++) acc[ni][r] = 0.f;

            const uint32_t a_base = ks_addr + ((q0 + a_row) * KLD + a_coff) * 4;
            const uint32_t b_base = ks_addr + (b_row * KLD + b_coff) * 4;

            #pragma unroll
            for (int ks = 0; ks < 8; ks++) {
                const uint32_t kc4 = (uint32_t)(ks * 8) * 4;
                uint32_t a0, a1, a2, a3;
                LDSM_X4(a0, a1, a2, a3, a_base + kc4);
                #pragma unroll
                for (int p = 0; p < 5; p++) {
                    uint32_t b0, b1, b2, b3;
                    LDSM_X4(b0, b1, b2, b3,
                            b_base + (uint32_t)(p * 16 * KLD) * 4 + kc4);
                    MMA_TF32(acc[2*p    ], a0, a1, a2, a3, b0, b1);
                    MMA_TF32(acc[2*p + 1], a0, a1, a2, a3, b2, b3);
                }
            }
            const int row0 = mi * 16 + g;
            #pragma unroll
            for (int ni = 0; ni < 10; ni++) {
                int col = qtr * 80 + ni * 8 + 2 * tig;
                Ssf[row0 * SLD + col    ] = (col     < NN) ? acc[ni][0] * scale : -1e30f;
                Ssf[row0 * SLD + col + 1] = (col + 1 < NN) ? acc[ni][1] * scale : -1e30f;
                Ssf[(row0+8) * SLD + col    ] = (col     < NN) ? acc[ni][2] * scale : -1e30f;
                Ssf[(row0+8) * SLD + col + 1] = (col + 1 < NN) ? acc[ni][3] * scale : -1e30f;
            }
        }
        __syncthreads();

        // ---- softmax: warp w -> rows [4w, 4w+4) ----
        #pragma unroll
        for (int r = 0; r < 4; r++) {
            const int row = w * 4 + r;
            float* srow = Ssf + row * SLD;
            float v[10];
            float mx = -1e30f;
            #pragma unroll
            for (int j = 0; j < 10; j++) {
                float s = srow[lane + 32 * j];
                v[j] = s;
                mx = fmaxf(mx, s);
            }
            #pragma unroll
            for (int off = 16; off; off >>= 1)
                mx = fmaxf(mx, __shfl_xor_sync(0xffffffffu, mx, off));
            float sum = 0.f;
            #pragma unroll
            for (int j = 0; j < 10; j++) {
                float ev = __expf(v[j] - mx);
                v[j] = ev;
                sum += ev;
            }
            #pragma unroll
            for (int off = 16; off; off >>= 1)
                sum += __shfl_xor_sync(0xffffffffu, sum, off);
            float inv = 1.f / sum;
            #pragma unroll
            for (int j = 0; j < 10; j++)
                SsB[row * SLD + lane + 32 * j] = f2tf(v[j] * inv);
        }
        __syncthreads();

        // ---- O = P K : 38 k-steps (keys 304..319 have exactly-zero prob) ----
        {
            float oacc[2][4];
            #pragma unroll
            for (int ni = 0; ni < 2; ni++)
                #pragma unroll
                for (int r = 0; r < 4; r++) oacc[ni][r] = 0.f;

            const uint32_t pa_base = ss_addr + (a_row * SLD + a_coff) * 4;
            const int ch0 = qtr * 16 + g;

            #pragma unroll 2
            for (int ks = 0; ks < 38; ks++) {
                const int kc = ks * 8;
                uint32_t a0, a1, a2, a3;
                LDSM_X4(a0, a1, a2, a3, pa_base + (uint32_t)kc * 4);
                uint32_t b00 = Ks[(kc + tig    ) * KLD + ch0    ];
                uint32_t b01 = Ks[(kc + tig + 4) * KLD + ch0    ];
                uint32_t b10 = Ks[(kc + tig    ) * KLD + ch0 + 8];
                uint32_t b11 = Ks[(kc + tig + 4) * KLD + ch0 + 8];
                MMA_TF32(oacc[0], a0, a1, a2, a3, b00, b01);
                MMA_TF32(oacc[1], a0, a1, a2, a3, b10, b11);
            }
            const int q = q0 + mi * 16 + g;
            float* ob = o + (size_t)b * NN * DDIM + h * DHD;
            #pragma unroll
            for (int ni = 0; ni < 2; ni++) {
                int ch = qtr * 16 + ni * 8 + 2 * tig;
                if (q < NN)
                    *(float2*)(ob + (size_t)q * DDIM + ch) =
                        make_float2(oacc[ni][0], oacc[ni][1]);
                if (q + 8 < NN)
                    *(float2*)(ob + (size_t)(q + 8) * DDIM + ch) =
                        make_float2(oacc[ni][2], oacc[ni][3]);
            }
        }
        __syncthreads();
    }
}

// ---------------- residual + LayerNorm ----------------
__global__ __launch_bounds__(256)
void ln_kernel(const float* __restrict__ a, const float* __restrict__ b,
               const float* __restrict__ gamma, const float* __restrict__ beta,
               float* __restrict__ out)
{
    int w    = threadIdx.x >> 5;
    int lane = threadIdx.x & 31;
    int row  = blockIdx.x * 8 + w;

    const float4* a4 = (const float4*)(a + (size_t)row * DDIM);
    const float4* b4 = (const float4*)(b + (size_t)row * DDIM);
    float4 v[4];
    float s1 = 0.f, s2 = 0.f;
    #pragma unroll
    for (int j = 0; j < 4; j++) {
        float4 av = a4[j * 32 + lane];
        float4 bv = b4[j * 32 + lane];
        float4 t = make_float4(av.x + bv.x, av.y + bv.y, av.z + bv.z, av.w + bv.w);
        v[j] = t;
        s1 += t.x + t.y + t.z + t.w;
        s2 += t.x * t.x + t.y * t.y + t.z * t.z + t.w * t.w;
    }
    #pragma unroll
    for (int off = 16; off; off >>= 1) {
        s1 += __shfl_xor_sync(0xffffffffu, s1, off);
        s2 += __shfl_xor_sync(0xffffffffu, s2, off);
    }
    float mean = s1 * (1.f / DDIM);
    float var  = s2 * (1.f / DDIM) - mean * mean;
    float rs   = rsqrtf(var + 1e-5f);

    const float4* g4  = (const float4*)gamma;
    const float4* be4 = (const float4*)beta;
    float4* o4 = (float4*)(out + (size_t)row * DDIM);
    #pragma unroll
    for (int j = 0; j < 4; j++) {
        float4 g = g4[j * 32 + lane];
        float4 be = be4[j * 32 + lane];
        float4 t = v[j];
        float4 r;
        r.x = (t.x - mean) * rs * g.x + be.x;
        r.y = (t.y - mean) * rs * g.y + be.y;
        r.z = (t.z - mean) * rs * g.z + be.z;
        r.w = (t.w - mean) * rs * g.w + be.w;
        o4[j * 32 + lane] = r;
    }
}

// ---------------- launcher ----------------
extern "C" void kernel_launch(void* const* d_in, const int* in_sizes, int n_in,
                              void* d_out, int out_size)
{
    const int*   tokens = (const int*)  d_in[0];
    const float* emb    = (const float*)d_in[1];
    const float* pos    = (const float*)d_in[2];
    const float* Wk     = (const float*)d_in[3];
    const float* Wo     = (const float*)d_in[4];
    const float* W1     = (const float*)d_in[5];
    const float* b1     = (const float*)d_in[6];
    const float* W2     = (const float*)d_in[7];
    const float* b2     = (const float*)d_in[8];
    const float* gamma  = (const float*)d_in[9];
    const float* beta   = (const float*)d_in[10];

    float *x, *k, *o, *z, *h;
    uint32_t* wr;
    cudaGetSymbolAddress((void**)&x,  g_x);
    cudaGetSymbolAddress((void**)&k,  g_k);
    cudaGetSymbolAddress((void**)&o,  g_o);
    cudaGetSymbolAddress((void**)&z,  g_z);
    cudaGetSymbolAddress((void**)&h,  g_h);
    cudaGetSymbolAddress((void**)&wr, g_wr);

    cudaFuncSetAttribute(attn_mma_kernel,
                         cudaFuncAttributeMaxDynamicSharedMemorySize, ATTN_SMEM);
    cudaFuncSetAttribute(mma_gemm_kernel,
                         cudaFuncAttributeMaxDynamicSharedMemorySize, GEMM_SMEM);

    // weight pre-round (all layers, once per launch)
    round_pack_wk_kernel<<<(LLAY * DDIM * DDIM) / 256, 256>>>(Wk, wr + WK_OFF);
    round_copy_kernel<<<(LLAY * DDIM * DDIM / 4 + 255) / 256, 256>>>(
        Wo, wr + WO_OFF, LLAY * DDIM * DDIM / 4);
    round_copy_kernel<<<(LLAY * DDIM * DFF / 4 + 255) / 256, 256>>>(
        W1, wr + W1_OFF, LLAY * DDIM * DFF / 4);
    round_copy_kernel<<<(LLAY * DDIM * DFF / 4 + 255) / 256, 256>>>(
        W2, wr + W2_OFF, LLAY * DDIM * DFF / 4);

    embed_kernel<<<(MM * 128) / 256, 256>>>(tokens, emb, pos, x);

    for (int l = 0; l < LLAY; l++) {
        mma_gemm_kernel<<<dim3(DDIM / 128, MM / 128), 256, GEMM_SMEM>>>(
            x, wr + WK_OFF + (size_t)l * DDIM * DDIM, k, MM, DDIM, DDIM,
            nullptr, 0);

        attn_mma_kernel<<<BB * HH, 512, ATTN_SMEM>>>(k, o);

        mma_gemm_kernel<<<dim3(DDIM / 128, MM / 128), 256, GEMM_SMEM>>>(
            o, wr + WO_OFF + (size_t)l * DDIM * DDIM, h, MM, DDIM, DDIM,
            nullptr, 0);

        ln_kernel<<<MM / 8, 256>>>(h, x, gamma + (size_t)l * DDIM,
                                   beta + (size_t)l * DDIM, z);

        mma_gemm_kernel<<<dim3(DFF / 128, MM / 128), 256, GEMM_SMEM>>>(
            z, wr + W1_OFF + (size_t)l * DDIM * DFF, h, MM, DFF, DDIM,
            b1 + (size_t)l * DFF, 1);

        mma_gemm_kernel<<<dim3(DDIM / 128, MM / 128), 256, GEMM_SMEM>>>(
            h, wr + W2_OFF + (size_t)l * DFF * DDIM, k, MM, DDIM, DFF,
            b2 + (size_t)l * DDIM, 0);

        float* dst = (l == LLAY - 1) ? (float*)d_out : x;
        ln_kernel<<<MM / 8, 256>>>(k, z, gamma + (size_t)l * DDIM,
                                   beta + (size_t)l * DDIM, dst);
    }
}

// round 12
// speedup vs baseline: 1.0885x; 1.0573x over previous
#include <cuda_runtime.h>
#include <cstddef>
#include <cstdint>

// Problem constants
#define BB   64
#define NN   300
#define DDIM 512
#define HH   8
#define DHD  64
#define LLAY 6
#define DFF  2048
#define MM   (BB*NN)   // 19200 rows

// ---------------- scratch (no allocation allowed) ----------------
__device__ float g_x [MM*DDIM];
__device__ float g_k [MM*DDIM];
__device__ float g_o [MM*DDIM];
__device__ float g_z [MM*DDIM];
__device__ float g_h [(size_t)MM*DFF];
// pre-rounded (tf32-RNA) weights, [K][N] row-major, fp32 bit patterns
#define WK_OFF 0
#define WO_OFF (LLAY*DDIM*DDIM)
#define W1_OFF (2*LLAY*DDIM*DDIM)
#define W2_OFF (2*LLAY*DDIM*DDIM + LLAY*DDIM*DFF)
__device__ uint32_t g_wr[2*LLAY*DDIM*DDIM + 2*LLAY*DDIM*DFF];

__device__ __forceinline__ uint32_t f2tf(float x) {
    uint32_t r;
    asm("cvt.rna.tf32.f32 %0, %1;" : "=r"(r) : "f"(x));
    return r;
}

__device__ __forceinline__ void cp_async16(uint32_t smem_addr, const void* gptr) {
    asm volatile("cp.async.cg.shared.global [%0], [%1], 16;\n"
                 :: "r"(smem_addr), "l"(gptr));
}

#define MMA_TF32(acc, a0,a1,a2,a3, b0,b1)                                   \
    asm volatile(                                                           \
        "mma.sync.aligned.m16n8k8.row.col.f32.tf32.tf32.f32 "               \
        "{%0,%1,%2,%3}, {%4,%5,%6,%7}, {%8,%9}, {%0,%1,%2,%3};"             \
        : "+f"(acc[0]), "+f"(acc[1]), "+f"(acc[2]), "+f"(acc[3])            \
        : "r"(a0), "r"(a1), "r"(a2), "r"(a3), "r"(b0), "r"(b1))

#define LDSM_X4(r0,r1,r2,r3, addr)                                          \
    asm volatile(                                                           \
        "ldmatrix.sync.aligned.m8n8.x4.shared.b16 {%0,%1,%2,%3}, [%4];"     \
        : "=r"(r0), "=r"(r1), "=r"(r2), "=r"(r3) : "r"(addr))

// ---------------- embed: x = emb[tok] + pos (tf32-RNA rounded) ----------------
__global__ void embed_kernel(const int* __restrict__ tok,
                             const float* __restrict__ emb,
                             const float* __restrict__ pos,
                             float* __restrict__ x)
{
    int gid = blockIdx.x * blockDim.x + threadIdx.x;
    int row = gid >> 7;
    int c   = gid & 127;
    int t   = tok[row];
    int n   = row % NN;
    float4 e = ((const float4*)emb)[(size_t)t * 128 + c];
    float4 p = ((const float4*)pos)[(size_t)n * 128 + c];
    float4 v;
    v.x = __uint_as_float(f2tf(e.x + p.x));
    v.y = __uint_as_float(f2tf(e.y + p.y));
    v.z = __uint_as_float(f2tf(e.z + p.z));
    v.w = __uint_as_float(f2tf(e.w + p.w));
    ((float4*)x)[gid] = v;
}

// ---------------- weight pre-round (RNA tf32), plain copy [K][N] ----------------
__global__ void round_copy_kernel(const float* __restrict__ in,
                                  uint32_t* __restrict__ out, int n4)
{
    int idx = blockIdx.x * blockDim.x + threadIdx.x;
    if (idx >= n4) return;
    float4 v = ((const float4*)in)[idx];
    uint4 r;
    r.x = f2tf(v.x); r.y = f2tf(v.y); r.z = f2tf(v.z); r.w = f2tf(v.w);
    ((uint4*)out)[idx] = r;
}

// ---------------- Wk pre-round + pack (H,D,DH) -> [K=D][N=H*DH], all layers ----------------
__global__ void round_pack_wk_kernel(const float* __restrict__ wk,
                                     uint32_t* __restrict__ out)
{
    int idx = blockIdx.x * blockDim.x + threadIdx.x;   // over LLAY*DDIM*DDIM
    int e = idx & (DDIM * DDIM - 1);
    int l = idx >> 18;
    int d = e >> 9;
    int c = e & 511;
    float v = wk[(size_t)l * (HH * DDIM * DHD) +
                 (size_t)(c >> 6) * (DDIM * DHD) + (size_t)d * DHD + (c & 63)];
    out[idx] = f2tf(v);
}

// ---------------- tf32 tensor-core GEMM, BM=128, BK=32, 2-stage (round-8 pipeline) ----------------
// A [M][K] fp32 — values already tf32-RNA at producers, loaded as raw bits.
// B [K][N] pre-rounded bits (raw loads).
#define BKK     32
#define ASTRIDE 36            // 128 rows; LDSM row banks 4i mod 32 distinct
#define BSTRIDE 136           // 32 rows; scalar B banks 8*tig+g distinct
#define A_STAGE (128*ASTRIDE) // floats
#define B_STAGE (BKK*BSTRIDE)
#define GEMM_SMEM ((2*(A_STAGE + B_STAGE)) * 4)

__global__ __launch_bounds__(256)
void mma_gemm_kernel(const float* __restrict__ A, const uint32_t* __restrict__ Bm,
                     float* __restrict__ C, int Mdim, int Ndim, int Kdim,
                     const float* __restrict__ bias, int relu, int round_out)
{
    extern __shared__ float dsm[];
    float*    Asm = dsm;                       // 2 stages
    uint32_t* Bsm = (uint32_t*)(dsm + 2 * A_STAGE);

    const int tid  = threadIdx.x;
    const int lane = tid & 31;
    const int w    = tid >> 5;
    const int g    = lane >> 2;
    const int tig  = lane & 3;

    const int warp_m = (w & 1) * 64;
    const int warp_n = (w >> 1) * 32;

    const int cRow = blockIdx.y * 128;
    const int cCol = blockIdx.x * 128;

    // A copy: 1024 16B-chunks (128 rows x 8), 4 per thread
    const int ar0 = tid >> 3;
    const int ac0 = (tid & 7) * 4;
    // B copy: 1024 16B-chunks (32 rows x 32), 4 per thread
    const int br0 = tid >> 5;
    const int bc0 = (tid & 31) * 4;

    const float*    Ag = A  + (size_t)cRow * Kdim;
    const uint32_t* Bg = Bm + cCol;

    const uint32_t as_base = (uint32_t)__cvta_generic_to_shared(Asm);
    const uint32_t a_ld_off =
        ((uint32_t)(warp_m + (lane & 15)) * ASTRIDE + ((lane >> 4) << 2)) * 4;

    float acc[4][4][4];
    #pragma unroll
    for (int mi = 0; mi < 4; mi++)
        #pragma unroll
        for (int ni = 0; ni < 4; ni++)
            #pragma unroll
            for (int r = 0; r < 4; r++) acc[mi][ni][r] = 0.f;

    const int ktiles = Kdim >> 5;

    // prologue: tile 0 -> buf 0
    {
        #pragma unroll
        for (int i = 0; i < 4; i++) {
            int arow = ar0 + i * 32;
            cp_async16((uint32_t)__cvta_generic_to_shared(Asm + arow * ASTRIDE + ac0),
                       Ag + (size_t)arow * Kdim + ac0);
            int brow = br0 + i * 8;
            cp_async16((uint32_t)__cvta_generic_to_shared(Bsm + brow * BSTRIDE + bc0),
                       Bg + (size_t)brow * Ndim + bc0);
        }
        asm volatile("cp.async.commit_group;\n");
    }

    for (int t = 0; t < ktiles; t++) {
        if (t + 1 < ktiles) {
            const int nb = (t + 1) & 1;
            const int k0 = (t + 1) << 5;
            float*    Asw = Asm + nb * A_STAGE;
            uint32_t* Bsw = Bsm + nb * B_STAGE;
            #pragma unroll
            for (int i = 0; i < 4; i++) {
                int arow = ar0 + i * 32;
                cp_async16((uint32_t)__cvta_generic_to_shared(Asw + arow * ASTRIDE + ac0),
                           Ag + (size_t)arow * Kdim + k0 + ac0);
                int brow = br0 + i * 8;
                cp_async16((uint32_t)__cvta_generic_to_shared(Bsw + brow * BSTRIDE + bc0),
                           Bg + (size_t)(k0 + brow) * Ndim + bc0);
            }
            asm volatile("cp.async.commit_group;\n");
            asm volatile("cp.async.wait_group 1;\n");
        } else {
            asm volatile("cp.async.wait_group 0;\n");
        }
        __syncthreads();

        const int buf = t & 1;
        const uint32_t a_stage = as_base + (uint32_t)(buf * A_STAGE) * 4 + a_ld_off;
        const uint32_t* bstage = Bsm + buf * B_STAGE;
        #pragma unroll
        for (int s = 0; s < 4; s++) {
            const int k8 = s * 8;
            uint32_t af[4][4];
            #pragma unroll
            for (int mi = 0; mi < 4; mi++)
                LDSM_X4(af[mi][0], af[mi][1], af[mi][2], af[mi][3],
                        a_stage + (uint32_t)(mi * 16 * ASTRIDE + k8) * 4);
            uint32_t bf[4][2];
            #pragma unroll
            for (int ni = 0; ni < 4; ni++) {
                int cb = warp_n + ni * 8 + g;
                bf[ni][0] = bstage[(k8 + tig    ) * BSTRIDE + cb];
                bf[ni][1] = bstage[(k8 + tig + 4) * BSTRIDE + cb];
            }
            #pragma unroll
            for (int mi = 0; mi < 4; mi++)
                #pragma unroll
                for (int ni = 0; ni < 4; ni++)
                    MMA_TF32(acc[mi][ni], af[mi][0], af[mi][1], af[mi][2], af[mi][3],
                             bf[ni][0], bf[ni][1]);
        }
        __syncthreads();
    }

    #pragma unroll
    for (int mi = 0; mi < 4; mi++) {
        int row0 = cRow + warp_m + mi * 16 + g;
        #pragma unroll
        for (int ni = 0; ni < 4; ni++) {
            int col = cCol + warp_n + ni * 8 + 2 * tig;
            float2 v0 = make_float2(acc[mi][ni][0], acc[mi][ni][1]);
            float2 v1 = make_float2(acc[mi][ni][2], acc[mi][ni][3]);
            if (bias) {
                float2 bb = *(const float2*)(bias + col);
                v0.x += bb.x; v0.y += bb.y;
                v1.x += bb.x; v1.y += bb.y;
            }
            if (relu) {
                v0.x = fmaxf(v0.x, 0.f); v0.y = fmaxf(v0.y, 0.f);
                v1.x = fmaxf(v1.x, 0.f); v1.y = fmaxf(v1.y, 0.f);
            }
            if (round_out) {
                v0.x = __uint_as_float(f2tf(v0.x));
                v0.y = __uint_as_float(f2tf(v0.y));
                v1.x = __uint_as_float(f2tf(v1.x));
                v1.y = __uint_as_float(f2tf(v1.y));
            }
            *(float2*)(C + (size_t)row0       * Ndim + col) = v0;
            *(float2*)(C + (size_t)(row0 + 8) * Ndim + col) = v1;
        }
    }
}

// ---------------- tensor-core attention (512 threads, ldmatrix, RNA at load) ----------------
#define KPAD   320
#define KLD    68
#define SLD    324
#define MQ     64
#define ATTN_SMEM ((KPAD*KLD + MQ*SLD) * 4)

__global__ __launch_bounds__(512, 1)
void attn_mma_kernel(const float* __restrict__ k, float* __restrict__ o)
{
    extern __shared__ uint32_t smu[];
    uint32_t* Ks  = smu;                    // KPAD*KLD tf32 bits (RNA at load)
    uint32_t* SsB = smu + KPAD * KLD;       // MQ*SLD (bits view)
    float*    Ssf = (float*)SsB;

    const int bh = blockIdx.x;
    const int b  = bh / HH, h = bh % HH;
    const float* kbase = k + (size_t)b * NN * DDIM + h * DHD;

    const int tid  = threadIdx.x;
    const int lane = tid & 31;
    const int w    = tid >> 5;      // 0..15
    const int g    = lane >> 2;
    const int tig  = lane & 3;

    const uint32_t ks_addr = (uint32_t)__cvta_generic_to_shared(Ks);
    const uint32_t ss_addr = (uint32_t)__cvta_generic_to_shared(SsB);

    for (int i = tid; i < KPAD * DHD; i += 512) {
        int m = i >> 6, e = i & 63;
        float v = (m < NN) ? kbase[(size_t)m * DDIM + e] : 0.f;
        Ks[m * KLD + e] = f2tf(v);
    }
    __syncthreads();

    const float scale = 0.04419417382415922f;   // 1/sqrt(512)
    const int mi  = w & 3;
    const int qtr = w >> 2;

    const uint32_t a_row  = (uint32_t)(mi * 16 + (lane & 15));
    const uint32_t a_coff = (uint32_t)((lane >> 4) << 2);
    const uint32_t b_row  = (uint32_t)(qtr * 80 + (lane & 7) + ((lane & 16) >> 1));
    const uint32_t b_coff = (uint32_t)((lane & 8) >> 1);

    for (int it = 0; it < 5; it++) {
        const int q0 = it * MQ;

        // ---- S = Q K^T ----
        {
            float acc[10][4];
            #pragma unroll
            for (int ni = 0; ni < 10; ni++)
                #pragma unroll
                for (int r = 0; r < 4; r++) acc[ni][r] = 0.f;

            const uint32_t a_base = ks_addr + ((q0 + a_row) * KLD + a_coff) * 4;
            const uint32_t b_base = ks_addr + (b_row * KLD + b_coff) * 4;

            #pragma unroll
            for (int ks = 0; ks < 8; ks++) {
                const uint32_t kc4 = (uint32_t)(ks * 8) * 4;
                uint32_t a0, a1, a2, a3;
                LDSM_X4(a0, a1, a2, a3, a_base + kc4);
                #pragma unroll
                for (int p = 0; p < 5; p++) {
                    uint32_t b0, b1, b2, b3;
                    LDSM_X4(b0, b1, b2, b3,
                            b_base + (uint32_t)(p * 16 * KLD) * 4 + kc4);
                    MMA_TF32(acc[2*p    ], a0, a1, a2, a3, b0, b1);
                    MMA_TF32(acc[2*p + 1], a0, a1, a2, a3, b2, b3);
                }
            }
            const int row0 = mi * 16 + g;
            #pragma unroll
            for (int ni = 0; ni < 10; ni++) {
                int col = qtr * 80 + ni * 8 + 2 * tig;
                Ssf[row0 * SLD + col    ] = (col     < NN) ? acc[ni][0] * scale : -1e30f;
                Ssf[row0 * SLD + col + 1] = (col + 1 < NN) ? acc[ni][1] * scale : -1e30f;
                Ssf[(row0+8) * SLD + col    ] = (col     < NN) ? acc[ni][2] * scale : -1e30f;
                Ssf[(row0+8) * SLD + col + 1] = (col + 1 < NN) ? acc[ni][3] * scale : -1e30f;
            }
        }
        __syncthreads();

        // ---- softmax: warp w -> rows [4w, 4w+4) ----
        #pragma unroll
        for (int r = 0; r < 4; r++) {
            const int row = w * 4 + r;
            float* srow = Ssf + row * SLD;
            float v[10];
            float mx = -1e30f;
            #pragma unroll
            for (int j = 0; j < 10; j++) {
                float s = srow[lane + 32 * j];
                v[j] = s;
                mx = fmaxf(mx, s);
            }
            #pragma unroll
            for (int off = 16; off; off >>= 1)
                mx = fmaxf(mx, __shfl_xor_sync(0xffffffffu, mx, off));
            float sum = 0.f;
            #pragma unroll
            for (int j = 0; j < 10; j++) {
                float ev = __expf(v[j] - mx);
                v[j] = ev;
                sum += ev;
            }
            #pragma unroll
            for (int off = 16; off; off >>= 1)
                sum += __shfl_xor_sync(0xffffffffu, sum, off);
            float inv = 1.f / sum;
            #pragma unroll
            for (int j = 0; j < 10; j++)
                SsB[row * SLD + lane + 32 * j] = f2tf(v[j] * inv);
        }
        __syncthreads();

        // ---- O = P K : 38 k-steps (keys 304..319 have exactly-zero prob) ----
        {
            float oacc[2][4];
            #pragma unroll
            for (int ni = 0; ni < 2; ni++)
                #pragma unroll
                for (int r = 0; r < 4; r++) oacc[ni][r] = 0.f;

            const uint32_t pa_base = ss_addr + (a_row * SLD + a_coff) * 4;
            const int ch0 = qtr * 16 + g;

            #pragma unroll 2
            for (int ks = 0; ks < 38; ks++) {
                const int kc = ks * 8;
                uint32_t a0, a1, a2, a3;
                LDSM_X4(a0, a1, a2, a3, pa_base + (uint32_t)kc * 4);
                uint32_t b00 = Ks[(kc + tig    ) * KLD + ch0    ];
                uint32_t b01 = Ks[(kc + tig + 4) * KLD + ch0    ];
                uint32_t b10 = Ks[(kc + tig    ) * KLD + ch0 + 8];
                uint32_t b11 = Ks[(kc + tig + 4) * KLD + ch0 + 8];
                MMA_TF32(oacc[0], a0, a1, a2, a3, b00, b01);
                MMA_TF32(oacc[1], a0, a1, a2, a3, b10, b11);
            }
            const int q = q0 + mi * 16 + g;
            float* ob = o + (size_t)b * NN * DDIM + h * DHD;
            #pragma unroll
            for (int ni = 0; ni < 2; ni++) {
                int ch = qtr * 16 + ni * 8 + 2 * tig;
                // round O to tf32-RNA: same rounding point the Wo GEMM's
                // per-fragment cvt applied before; now amortized here.
                float2 v0 = make_float2(__uint_as_float(f2tf(oacc[ni][0])),
                                        __uint_as_float(f2tf(oacc[ni][1])));
                float2 v1 = make_float2(__uint_as_float(f2tf(oacc[ni][2])),
                                        __uint_as_float(f2tf(oacc[ni][3])));
                if (q < NN)
                    *(float2*)(ob + (size_t)q * DDIM + ch) = v0;
                if (q + 8 < NN)
                    *(float2*)(ob + (size_t)(q + 8) * DDIM + ch) = v1;
            }
        }
        __syncthreads();
    }
}

// ---------------- residual + LayerNorm (optional tf32-RNA output) ----------------
__global__ __launch_bounds__(256)
void ln_kernel(const float* __restrict__ a, const float* __restrict__ b,
               const float* __restrict__ gamma, const float* __restrict__ beta,
               float* __restrict__ out, int round_out)
{
    int w    = threadIdx.x >> 5;
    int lane = threadIdx.x & 31;
    int row  = blockIdx.x * 8 + w;

    const float4* a4 = (const float4*)(a + (size_t)row * DDIM);
    const float4* b4 = (const float4*)(b + (size_t)row * DDIM);
    float4 v[4];
    float s1 = 0.f, s2 = 0.f;
    #pragma unroll
    for (int j = 0; j < 4; j++) {
        float4 av = a4[j * 32 + lane];
        float4 bv = b4[j * 32 + lane];
        float4 t = make_float4(av.x + bv.x, av.y + bv.y, av.z + bv.z, av.w + bv.w);
        v[j] = t;
        s1 += t.x + t.y + t.z + t.w;
        s2 += t.x * t.x + t.y * t.y + t.z * t.z + t.w * t.w;
    }
    #pragma unroll
    for (int off = 16; off; off >>= 1) {
        s1 += __shfl_xor_sync(0xffffffffu, s1, off);
        s2 += __shfl_xor_sync(0xffffffffu, s2, off);
    }
    float mean = s1 * (1.f / DDIM);
    float var  = s2 * (1.f / DDIM) - mean * mean;
    float rs   = rsqrtf(var + 1e-5f);

    const float4* g4  = (const float4*)gamma;
    const float4* be4 = (const float4*)beta;
    float4* o4 = (float4*)(out + (size_t)row * DDIM);
    #pragma unroll
    for (int j = 0; j < 4; j++) {
        float4 g = g4[j * 32 + lane];
        float4 be = be4[j * 32 + lane];
        float4 t = v[j];
        float4 r;
        r.x = (t.x - mean) * rs * g.x + be.x;
        r.y = (t.y - mean) * rs * g.y + be.y;
        r.z = (t.z - mean) * rs * g.z + be.z;
        r.w = (t.w - mean) * rs * g.w + be.w;
        if (round_out) {
            r.x = __uint_as_float(f2tf(r.x));
            r.y = __uint_as_float(f2tf(r.y));
            r.z = __uint_as_float(f2tf(r.z));
            r.w = __uint_as_float(f2tf(r.w));
        }
        o4[j * 32 + lane] = r;
    }
}

// ---------------- launcher ----------------
extern "C" void kernel_launch(void* const* d_in, const int* in_sizes, int n_in,
                              void* d_out, int out_size)
{
    const int*   tokens = (const int*)  d_in[0];
    const float* emb    = (const float*)d_in[1];
    const float* pos    = (const float*)d_in[2];
    const float* Wk     = (const float*)d_in[3];
    const float* Wo     = (const float*)d_in[4];
    const float* W1     = (const float*)d_in[5];
    const float* b1     = (const float*)d_in[6];
    const float* W2     = (const float*)d_in[7];
    const float* b2     = (const float*)d_in[8];
    const float* gamma  = (const float*)d_in[9];
    const float* beta   = (const float*)d_in[10];

    float *x, *k, *o, *z, *h;
    uint32_t* wr;
    cudaGetSymbolAddress((void**)&x,  g_x);
    cudaGetSymbolAddress((void**)&k,  g_k);
    cudaGetSymbolAddress((void**)&o,  g_o);
    cudaGetSymbolAddress((void**)&z,  g_z);
    cudaGetSymbolAddress((void**)&h,  g_h);
    cudaGetSymbolAddress((void**)&wr, g_wr);

    cudaFuncSetAttribute(attn_mma_kernel,
                         cudaFuncAttributeMaxDynamicSharedMemorySize, ATTN_SMEM);
    cudaFuncSetAttribute(mma_gemm_kernel,
                         cudaFuncAttributeMaxDynamicSharedMemorySize, GEMM_SMEM);

    // weight pre-round (all layers, once per launch)
    round_pack_wk_kernel<<<(LLAY * DDIM * DDIM) / 256, 256>>>(Wk, wr + WK_OFF);
    round_copy_kernel<<<(LLAY * DDIM * DDIM / 4 + 255) / 256, 256>>>(
        Wo, wr + WO_OFF, LLAY * DDIM * DDIM / 4);
    round_copy_kernel<<<(LLAY * DDIM * DFF / 4 + 255) / 256, 256>>>(
        W1, wr + W1_OFF, LLAY * DDIM * DFF / 4);
    round_copy_kernel<<<(LLAY * DDIM * DFF / 4 + 255) / 256, 256>>>(
        W2, wr + W2_OFF, LLAY * DDIM * DFF / 4);

    embed_kernel<<<(MM * 128) / 256, 256>>>(tokens, emb, pos, x);

    for (int l = 0; l < LLAY; l++) {
        // K = X @ Wk[l]   (x pre-rounded; output unrounded, attn rounds at load)
        mma_gemm_kernel<<<dim3(DDIM / 128, MM / 128), 256, GEMM_SMEM>>>(
            x, wr + WK_OFF + (size_t)l * DDIM * DDIM, k, MM, DDIM, DDIM,
            nullptr, 0, 0);

        attn_mma_kernel<<<BB * HH, 512, ATTN_SMEM>>>(k, o);

        // h = O @ Wo  (o pre-rounded at attn store)
        mma_gemm_kernel<<<dim3(DDIM / 128, MM / 128), 256, GEMM_SMEM>>>(
            o, wr + WO_OFF + (size_t)l * DDIM * DDIM, h, MM, DDIM, DDIM,
            nullptr, 0, 0);

        // z = LN(h + x), rounded (feeds FFN1 A-side)
        ln_kernel<<<MM / 8, 256>>>(h, x, gamma + (size_t)l * DDIM,
                                   beta + (size_t)l * DDIM, z, 1);

        // h = relu(z @ W1 + b1), rounded in epilogue (feeds FFN2 A-side)
        mma_gemm_kernel<<<dim3(DFF / 128, MM / 128), 256, GEMM_SMEM>>>(
            z, wr + W1_OFF + (size_t)l * DDIM * DFF, h, MM, DFF, DDIM,
            b1 + (size_t)l * DFF, 1, 1);

        // k = h @ W2 + b2 (unrounded; feeds LN only)
        mma_gemm_kernel<<<dim3(DDIM / 128, MM / 128), 256, GEMM_SMEM>>>(
            h, wr + W2_OFF + (size_t)l * DFF * DDIM, k, MM, DDIM, DFF,
            b2 + (size_t)l * DDIM, 0, 0);

        // x = LN(k + z); non-final rounded (feeds next K-proj A-side)
        float* dst = (l == LLAY - 1) ? (float*)d_out : x;
        ln_kernel<<<MM / 8, 256>>>(k, z, gamma + (size_t)l * DDIM,
                                   beta + (size_t)l * DDIM, dst,
                                   (l == LLAY - 1) ? 0 : 1);
    }
}

// round 13
// speedup vs baseline: 1.9594x; 1.8001x over previous
#include <cuda_runtime.h>
#include <cuda_fp16.h>
#include <cstddef>
#include <cstdint>

// Problem constants
#define BB   64
#define NN   300
#define DDIM 512
#define HH   8
#define DHD  64
#define LLAY 6
#define DFF  2048
#define MM   (BB*NN)   // 19200 rows

// ---------------- scratch (no allocation allowed) ----------------
__device__ float  g_x [MM*DDIM];          // exact residual x (fp32)
__device__ float  g_z [MM*DDIM];          // exact z (fp32)
__device__ float  g_f [MM*DDIM];          // fp32 GEMM outputs (Wo-out / FFN2-out)
__device__ __half g_xh[MM*DDIM];          // half copy of x (GEMM A)
__device__ __half g_zh[MM*DDIM];          // half copy of z (GEMM A)
__device__ __half g_kh[MM*DDIM];          // K-proj out (half, attn input)
__device__ __half g_oh[MM*DDIM];          // attn out (half, Wo GEMM A)
__device__ __half g_hh[(size_t)MM*DFF];   // FFN hidden (half)
// half weights, [N][K] transposed
#define WK_OFF 0
#define WO_OFF (LLAY*DDIM*DDIM)
#define W1_OFF (2*LLAY*DDIM*DDIM)
#define W2_OFF (2*LLAY*DDIM*DDIM + LLAY*DDIM*DFF)
__device__ __half g_w[2*LLAY*DDIM*DDIM + 2*LLAY*DDIM*DFF];

__device__ __forceinline__ void cp_async16(uint32_t smem_addr, const void* gptr) {
    asm volatile("cp.async.cg.shared.global [%0], [%1], 16;\n"
                 :: "r"(smem_addr), "l"(gptr));
}

#define MMA_F16(acc, a0,a1,a2,a3, b0,b1)                                    \
    asm volatile(                                                           \
        "mma.sync.aligned.m16n8k16.row.col.f32.f16.f16.f32 "                \
        "{%0,%1,%2,%3}, {%4,%5,%6,%7}, {%8,%9}, {%0,%1,%2,%3};"             \
        : "+f"(acc[0]), "+f"(acc[1]), "+f"(acc[2]), "+f"(acc[3])            \
        : "r"(a0), "r"(a1), "r"(a2), "r"(a3), "r"(b0), "r"(b1))

#define LDSM_X4(r0,r1,r2,r3, addr)                                          \
    asm volatile(                                                           \
        "ldmatrix.sync.aligned.m8n8.x4.shared.b16 {%0,%1,%2,%3}, [%4];"     \
        : "=r"(r0), "=r"(r1), "=r"(r2), "=r"(r3) : "r"(addr))

#define LDSM_X2_T(r0,r1, addr)                                              \
    asm volatile(                                                           \
        "ldmatrix.sync.aligned.m8n8.x2.trans.shared.b16 {%0,%1}, [%2];"     \
        : "=r"(r0), "=r"(r1) : "r"(addr))

// ---------------- embed: x = emb[tok] + pos -> fp32 + half ----------------
__global__ void embed_kernel(const int* __restrict__ tok,
                             const float* __restrict__ emb,
                             const float* __restrict__ pos,
                             float* __restrict__ x, __half* __restrict__ xh)
{
    int gid = blockIdx.x * blockDim.x + threadIdx.x;
    int row = gid >> 7;
    int c   = gid & 127;
    int t   = tok[row];
    int n   = row % NN;
    float4 e = ((const float4*)emb)[(size_t)t * 128 + c];
    float4 p = ((const float4*)pos)[(size_t)n * 128 + c];
    float4 v = make_float4(e.x + p.x, e.y + p.y, e.z + p.z, e.w + p.w);
    ((float4*)x)[gid] = v;
    __half2* xh2 = (__half2*)(xh + (size_t)gid * 4);
    xh2[0] = __floats2half2_rn(v.x, v.y);
    xh2[1] = __floats2half2_rn(v.z, v.w);
}

// ---------------- weight transpose to half: in [K][N] fp32 -> out [N][K] half ----------------
__global__ void half_transpose_kernel(const float* __restrict__ in,
                                      __half* __restrict__ out, int K, int N)
{
    __shared__ float t[32][33];
    const size_t loff = (size_t)blockIdx.z * K * N;
    const int k0 = blockIdx.y * 32;
    const int n0 = blockIdx.x * 32;
    const int tx = threadIdx.x, ty = threadIdx.y;   // 32 x 8
    #pragma unroll
    for (int i = 0; i < 32; i += 8)
        t[ty + i][tx] = in[loff + (size_t)(k0 + ty + i) * N + n0 + tx];
    __syncthreads();
    #pragma unroll
    for (int i = 0; i < 32; i += 8)
        out[loff + (size_t)(n0 + ty + i) * K + k0 + tx] =
            __float2half_rn(t[tx][ty + i]);
}

// Wk (L,H,D,DH): logical [K=D][N=H*DH] -> out [N][K] half per layer
__global__ void half_transpose_wk_kernel(const float* __restrict__ wk,
                                         __half* __restrict__ out)
{
    __shared__ float t[32][33];
    const int l  = blockIdx.z;
    const int k0 = blockIdx.y * 32;
    const int n0 = blockIdx.x * 32;
    const float* w = wk + (size_t)l * HH * DDIM * DHD;
    const int tx = threadIdx.x, ty = threadIdx.y;
    #pragma unroll
    for (int i = 0; i < 32; i += 8) {
        int k = k0 + ty + i, n = n0 + tx;
        t[ty + i][tx] = w[(size_t)(n >> 6) * (DDIM * DHD) + (size_t)k * DHD + (n & 63)];
    }
    __syncthreads();
    #pragma unroll
    for (int i = 0; i < 32; i += 8)
        out[(size_t)l * DDIM * DDIM + (size_t)(n0 + ty + i) * DDIM + k0 + tx] =
            __float2half_rn(t[tx][ty + i]);
}

// ---------------- fp16 tensor-core GEMM: C[M,N] = A @ BT^T ----------------
// A [M][K] half, BT [N][K] half. BM=BN=128, BK=64, 2-stage cp.async.
#define ALD      72                      // half stride (144B = 9 x 16B: conflict-free)
#define STG_H    (128*ALD)               // halves per (A or B) stage
#define STG_B    (STG_H*2)               // bytes
#define GEMM_SMEM (4*STG_B)              // 2 stages A + 2 stages B = 73728 B

__global__ __launch_bounds__(256)
void gemm_f16_kernel(const __half* __restrict__ A, const __half* __restrict__ BT,
                     void* __restrict__ Cv, int Mdim, int Ndim, int Kdim,
                     const float* __restrict__ bias, int relu, int outHalf)
{
    extern __shared__ __half hsm[];
    __half* Asm = hsm;                    // 2 stages
    __half* Bsm = hsm + 2 * STG_H;        // 2 stages

    const int tid  = threadIdx.x;
    const int lane = tid & 31;
    const int w    = tid >> 5;
    const int g    = lane >> 2;
    const int tig  = lane & 3;

    const int warp_m = (w & 1) * 64;
    const int warp_n = (w >> 1) * 32;

    const int cRow = blockIdx.y * 128;
    const int cCol = blockIdx.x * 128;

    // copies: 128 rows x 8 pieces(16B) = 1024 pieces per matrix; 4 per thread
    const int r0 = tid >> 3;              // rows r0 + 32*j
    const int ci = tid & 7;               // 16B piece (8 halves)

    const __half* Ag = A  + (size_t)cRow * Kdim;
    const __half* Bg = BT + (size_t)cCol * Kdim;

    const uint32_t as_base = (uint32_t)__cvta_generic_to_shared(Asm);
    const uint32_t bs_base = (uint32_t)__cvta_generic_to_shared(Bsm);
    const uint32_t a_ld_off =
        ((uint32_t)(warp_m + (lane & 15)) * ALD + ((lane >> 4) << 3)) * 2;
    const uint32_t b_ld_off =
        ((uint32_t)(warp_n + ((lane >> 4) << 3) + (lane & 7)) * ALD
         + (((lane >> 3) & 1) << 3)) * 2;

    float acc[4][4][4];
    #pragma unroll
    for (int mi = 0; mi < 4; mi++)
        #pragma unroll
        for (int ni = 0; ni < 4; ni++)
            #pragma unroll
            for (int r = 0; r < 4; r++) acc[mi][ni][r] = 0.f;

    const int ktiles = Kdim >> 6;         // BK=64

    // prologue: tile 0 -> buf 0
    {
        #pragma unroll
        for (int j = 0; j < 4; j++) {
            int r = r0 + 32 * j;
            uint32_t so = (uint32_t)(r * ALD + ci * 8) * 2;
            cp_async16(as_base + so, Ag + (size_t)r * Kdim + ci * 8);
            cp_async16(bs_base + so, Bg + (size_t)r * Kdim + ci * 8);
        }
        asm volatile("cp.async.commit_group;\n");
    }

    for (int t = 0; t < ktiles; t++) {
        if (t + 1 < ktiles) {
            const int nb = (t + 1) & 1;
            const int kc = (t + 1) << 6;
            #pragma unroll
            for (int j = 0; j < 4; j++) {
                int r = r0 + 32 * j;
                uint32_t so = (uint32_t)(nb * STG_B) + (uint32_t)(r * ALD + ci * 8) * 2;
                cp_async16(as_base + so, Ag + (size_t)r * Kdim + kc + ci * 8);
                cp_async16(bs_base + so, Bg + (size_t)r * Kdim + kc + ci * 8);
            }
            asm volatile("cp.async.commit_group;\n");
            asm volatile("cp.async.wait_group 1;\n");
        } else {
            asm volatile("cp.async.wait_group 0;\n");
        }
        __syncthreads();

        const int buf = t & 1;
        const uint32_t a_stage = as_base + (uint32_t)(buf * STG_B) + a_ld_off;
        const uint32_t b_stage = bs_base + (uint32_t)(buf * STG_B) + b_ld_off;
        #pragma unroll
        for (int s = 0; s < 4; s++) {
            const uint32_t kofs = (uint32_t)s * 32;     // 16 halves
            uint32_t af[4][4];
            #pragma unroll
            for (int mi = 0; mi < 4; mi++)
                LDSM_X4(af[mi][0], af[mi][1], af[mi][2], af[mi][3],
                        a_stage + (uint32_t)(mi * 16 * ALD) * 2 + kofs);
            uint32_t bf[4][2];
            LDSM_X4(bf[0][0], bf[0][1], bf[1][0], bf[1][1], b_stage + kofs);
            LDSM_X4(bf[2][0], bf[2][1], bf[3][0], bf[3][1],
                    b_stage + (uint32_t)(16 * ALD) * 2 + kofs);
            #pragma unroll
            for (int mi = 0; mi < 4; mi++)
                #pragma unroll
                for (int ni = 0; ni < 4; ni++)
                    MMA_F16(acc[mi][ni], af[mi][0], af[mi][1], af[mi][2], af[mi][3],
                            bf[ni][0], bf[ni][1]);
        }
        __syncthreads();
    }

    // epilogue
    #pragma unroll
    for (int mi = 0; mi < 4; mi++) {
        int row0 = cRow + warp_m + mi * 16 + g;
        #pragma unroll
        for (int ni = 0; ni < 4; ni++) {
            int col = cCol + warp_n + ni * 8 + 2 * tig;
            float2 v0 = make_float2(acc[mi][ni][0], acc[mi][ni][1]);
            float2 v1 = make_float2(acc[mi][ni][2], acc[mi][ni][3]);
            if (bias) {
                float2 bb = *(const float2*)(bias + col);
                v0.x += bb.x; v0.y += bb.y;
                v1.x += bb.x; v1.y += bb.y;
            }
            if (relu) {
                v0.x = fmaxf(v0.x, 0.f); v0.y = fmaxf(v0.y, 0.f);
                v1.x = fmaxf(v1.x, 0.f); v1.y = fmaxf(v1.y, 0.f);
            }
            if (outHalf) {
                __half* Ch = (__half*)Cv;
                *(__half2*)(Ch + (size_t)row0       * Ndim + col) =
                    __floats2half2_rn(v0.x, v0.y);
                *(__half2*)(Ch + (size_t)(row0 + 8) * Ndim + col) =
                    __floats2half2_rn(v1.x, v1.y);
            } else {
                float* Cf = (float*)Cv;
                *(float2*)(Cf + (size_t)row0       * Ndim + col) = v0;
                *(float2*)(Cf + (size_t)(row0 + 8) * Ndim + col) = v1;
            }
        }
    }
}

// ---------------- fp16 tensor-core attention ----------------
// K tile [320][72] half; scores/probs [64][312] half. 512 threads, 16 warps.
#define KPAD   320
#define KLD2   72
#define PSLD   312
#define MQ     64
#define NKEY   304              // 19 k16 steps in O-phase
#define ATTN_SMEM ((KPAD*KLD2 + MQ*PSLD) * 2)

__global__ __launch_bounds__(512)
void attn_f16_kernel(const __half* __restrict__ k, __half* __restrict__ o)
{
    extern __shared__ __half smh[];
    __half* Ks = smh;                       // KPAD x KLD2
    __half* Ps = smh + KPAD * KLD2;         // MQ x PSLD

    const int bh = blockIdx.x;
    const int b  = bh / HH, h = bh % HH;
    const __half* kbase = k + (size_t)b * NN * DDIM + h * DHD;

    const int tid  = threadIdx.x;
    const int lane = tid & 31;
    const int w    = tid >> 5;      // 0..15
    const int g    = lane >> 2;
    const int tig  = lane & 3;

    const uint32_t ks_addr = (uint32_t)__cvta_generic_to_shared(Ks);
    const uint32_t ps_addr = (uint32_t)__cvta_generic_to_shared(Ps);

    // load K head tile (zero-pad rows >= NN); cols 64..71 never read
    for (int i = tid; i < KPAD * DHD; i += 512) {
        int m = i >> 6, e = i & 63;
        Ks[m * KLD2 + e] = (m < NN) ? kbase[(size_t)m * DDIM + e] : __half(0.f);
    }
    __syncthreads();

    const float scale = 0.04419417382415922f;   // 1/sqrt(512)
    const int mi  = w & 3;        // q m-tile
    const int qtr = w >> 2;       // key/channel quarter

    const uint32_t a_row  = (uint32_t)(lane & 15);
    const uint32_t a_coff = (uint32_t)((lane >> 4) << 3);    // halves
    const uint32_t bp_row = (uint32_t)(((lane >> 4) << 3) + (lane & 7));
    const uint32_t bp_cof = (uint32_t)(((lane >> 3) & 1) << 3);

    for (int it = 0; it < 5; it++) {
        const int q0 = it * MQ;

        // ---- S = Q K^T : 10 n8-tiles per warp, 4 k16 steps ----
        {
            float acc[10][4];
            #pragma unroll
            for (int ni = 0; ni < 10; ni++)
                #pragma unroll
                for (int r = 0; r < 4; r++) acc[ni][r] = 0.f;

            const uint32_t a_base = ks_addr +
                ((q0 + mi * 16 + a_row) * KLD2 + a_coff) * 2;
            const uint32_t b_base = ks_addr +
                ((qtr * 80 + bp_row) * KLD2 + bp_cof) * 2;

            #pragma unroll
            for (int s = 0; s < 4; s++) {
                const uint32_t kofs = (uint32_t)s * 32;   // 16 halves
                uint32_t a0, a1, a2, a3;
                LDSM_X4(a0, a1, a2, a3, a_base + kofs);
                #pragma unroll
                for (int p = 0; p < 5; p++) {
                    uint32_t b0, b1, b2, b3;
                    LDSM_X4(b0, b1, b2, b3,
                            b_base + (uint32_t)(p * 16 * KLD2) * 2 + kofs);
                    MMA_F16(acc[2*p    ], a0, a1, a2, a3, b0, b1);
                    MMA_F16(acc[2*p + 1], a0, a1, a2, a3, b2, b3);
                }
            }
            const int row0 = mi * 16 + g;
            #pragma unroll
            for (int ni = 0; ni < 10; ni++) {
                int col = qtr * 80 + ni * 8 + 2 * tig;
                if (col < NKEY) {
                    float s0 = (col     < NN) ? acc[ni][0] * scale : -60000.f;
                    float s1 = (col + 1 < NN) ? acc[ni][1] * scale : -60000.f;
                    float s2 = (col     < NN) ? acc[ni][2] * scale : -60000.f;
                    float s3 = (col + 1 < NN) ? acc[ni][3] * scale : -60000.f;
                    *(__half2*)(Ps + row0 * PSLD + col) = __floats2half2_rn(s0, s1);
                    *(__half2*)(Ps + (row0 + 8) * PSLD + col) = __floats2half2_rn(s2, s3);
                }
            }
        }
        __syncthreads();

        // ---- softmax: warp w -> rows [4w, 4w+4), 304 cols ----
        #pragma unroll
        for (int r = 0; r < 4; r++) {
            const int row = w * 4 + r;
            __half* prow = Ps + row * PSLD;
            float v[10];
            float mx = -1e30f;
            #pragma unroll
            for (int j = 0; j < 10; j++) {
                int c = lane + 32 * j;
                float s = (c < NKEY) ? __half2float(prow[c]) : -60000.f;
                v[j] = s;
                mx = fmaxf(mx, s);
            }
            #pragma unroll
            for (int off = 16; off; off >>= 1)
                mx = fmaxf(mx, __shfl_xor_sync(0xffffffffu, mx, off));
            float sum = 0.f;
            #pragma unroll
            for (int j = 0; j < 10; j++) {
                float ev = __expf(v[j] - mx);
                v[j] = ev;
                sum += ev;
            }
            #pragma unroll
            for (int off = 16; off; off >>= 1)
                sum += __shfl_xor_sync(0xffffffffu, sum, off);
            float inv = 1.f / sum;
            #pragma unroll
            for (int j = 0; j < 10; j++) {
                int c = lane + 32 * j;
                if (c < NKEY) prow[c] = __float2half_rn(v[j] * inv);
            }
        }
        __syncthreads();

        // ---- O = P K : 2 n8-tiles (16 channels) per warp, 19 k16 steps ----
        {
            float oacc[2][4];
            #pragma unroll
            for (int ni = 0; ni < 2; ni++)
                #pragma unroll
                for (int r = 0; r < 4; r++) oacc[ni][r] = 0.f;

            const uint32_t pa_base = ps_addr + ((mi * 16 + a_row) * PSLD + a_coff) * 2;
            const int ch0 = qtr * 16;
            const uint32_t kb_base = ks_addr + ((uint32_t)(lane & 15) * KLD2) * 2;

            #pragma unroll 1
            for (int s = 0; s < 19; s++) {
                const int kk = s * 16;
                uint32_t a0, a1, a2, a3;
                LDSM_X4(a0, a1, a2, a3, pa_base + (uint32_t)(kk) * 2);
                uint32_t b00, b01, b10, b11;
                LDSM_X2_T(b00, b01,
                          kb_base + ((uint32_t)(kk * KLD2) + ch0) * 2);
                LDSM_X2_T(b10, b11,
                          kb_base + ((uint32_t)(kk * KLD2) + ch0 + 8) * 2);
                MMA_F16(oacc[0], a0, a1, a2, a3, b00, b01);
                MMA_F16(oacc[1], a0, a1, a2, a3, b10, b11);
            }
            const int q = q0 + mi * 16 + g;
            __half* ob = o + (size_t)b * NN * DDIM + h * DHD;
            #pragma unroll
            for (int ni = 0; ni < 2; ni++) {
                int ch = ch0 + ni * 8 + 2 * tig;
                if (q < NN)
                    *(__half2*)(ob + (size_t)q * DDIM + ch) =
                        __floats2half2_rn(oacc[ni][0], oacc[ni][1]);
                if (q + 8 < NN)
                    *(__half2*)(ob + (size_t)(q + 8) * DDIM + ch) =
                        __floats2half2_rn(oacc[ni][2], oacc[ni][3]);
            }
        }
        __syncthreads();
    }
}

// ---------------- residual + LayerNorm: fp32 out (opt) + half out (opt) ----------------
__global__ __launch_bounds__(256)
void ln_kernel(const float* __restrict__ a, const float* __restrict__ b,
               const float* __restrict__ gamma, const float* __restrict__ beta,
               float* __restrict__ outf, __half* __restrict__ outh)
{
    int w    = threadIdx.x >> 5;
    int lane = threadIdx.x & 31;
    int row  = blockIdx.x * 8 + w;

    const float4* a4 = (const float4*)(a + (size_t)row * DDIM);
    const float4* b4 = (const float4*)(b + (size_t)row * DDIM);
    float4 v[4];
    float s1 = 0.f, s2 = 0.f;
    #pragma unroll
    for (int j = 0; j < 4; j++) {
        float4 av = a4[j * 32 + lane];
        float4 bv = b4[j * 32 + lane];
        float4 t = make_float4(av.x + bv.x, av.y + bv.y, av.z + bv.z, av.w + bv.w);
        v[j] = t;
        s1 += t.x + t.y + t.z + t.w;
        s2 += t.x * t.x + t.y * t.y + t.z * t.z + t.w * t.w;
    }
    #pragma unroll
    for (int off = 16; off; off >>= 1) {
        s1 += __shfl_xor_sync(0xffffffffu, s1, off);
        s2 += __shfl_xor_sync(0xffffffffu, s2, off);
    }
    float mean = s1 * (1.f / DDIM);
    float var  = s2 * (1.f / DDIM) - mean * mean;
    float rs   = rsqrtf(var + 1e-5f);

    const float4* g4  = (const float4*)gamma;
    const float4* be4 = (const float4*)beta;
    #pragma unroll
    for (int j = 0; j < 4; j++) {
        float4 g = g4[j * 32 + lane];
        float4 be = be4[j * 32 + lane];
        float4 t = v[j];
        float4 r;
        r.x = (t.x - mean) * rs * g.x + be.x;
        r.y = (t.y - mean) * rs * g.y + be.y;
        r.z = (t.z - mean) * rs * g.z + be.z;
        r.w = (t.w - mean) * rs * g.w + be.w;
        if (outf)
            ((float4*)(outf + (size_t)row * DDIM))[j * 32 + lane] = r;
        if (outh) {
            __half2* o2 = (__half2*)(outh + (size_t)row * DDIM) + (j * 32 + lane) * 2;
            o2[0] = __floats2half2_rn(r.x, r.y);
            o2[1] = __floats2half2_rn(r.z, r.w);
        }
    }
}

// ---------------- launcher ----------------
extern "C" void kernel_launch(void* const* d_in, const int* in_sizes, int n_in,
                              void* d_out, int out_size)
{
    const int*   tokens = (const int*)  d_in[0];
    const float* emb    = (const float*)d_in[1];
    const float* pos    = (const float*)d_in[2];
    const float* Wk     = (const float*)d_in[3];
    const float* Wo     = (const float*)d_in[4];
    const float* W1     = (const float*)d_in[5];
    const float* b1     = (const float*)d_in[6];
    const float* W2     = (const float*)d_in[7];
    const float* b2     = (const float*)d_in[8];
    const float* gamma  = (const float*)d_in[9];
    const float* beta   = (const float*)d_in[10];

    float *x, *z, *f;
    __half *xh, *zh, *kh, *oh, *hh, *wh;
    cudaGetSymbolAddress((void**)&x,  g_x);
    cudaGetSymbolAddress((void**)&z,  g_z);
    cudaGetSymbolAddress((void**)&f,  g_f);
    cudaGetSymbolAddress((void**)&xh, g_xh);
    cudaGetSymbolAddress((void**)&zh, g_zh);
    cudaGetSymbolAddress((void**)&kh, g_kh);
    cudaGetSymbolAddress((void**)&oh, g_oh);
    cudaGetSymbolAddress((void**)&hh, g_hh);
    cudaGetSymbolAddress((void**)&wh, g_w);

    cudaFuncSetAttribute(attn_f16_kernel,
                         cudaFuncAttributeMaxDynamicSharedMemorySize, ATTN_SMEM);
    cudaFuncSetAttribute(gemm_f16_kernel,
                         cudaFuncAttributeMaxDynamicSharedMemorySize, GEMM_SMEM);

    dim3 tb(32, 8);
    half_transpose_wk_kernel<<<dim3(DDIM/32, DDIM/32, LLAY), tb>>>(Wk, wh + WK_OFF);
    half_transpose_kernel<<<dim3(DDIM/32, DDIM/32, LLAY), tb>>>(Wo, wh + WO_OFF, DDIM, DDIM);
    half_transpose_kernel<<<dim3(DFF/32, DDIM/32, LLAY), tb>>>(W1, wh + W1_OFF, DDIM, DFF);
    half_transpose_kernel<<<dim3(DDIM/32, DFF/32, LLAY), tb>>>(W2, wh + W2_OFF, DFF, DDIM);

    embed_kernel<<<(MM * 128) / 256, 256>>>(tokens, emb, pos, x, xh);

    for (int l = 0; l < LLAY; l++) {
        // K = X @ Wk[l]^T  -> half
        gemm_f16_kernel<<<dim3(DDIM / 128, MM / 128), 256, GEMM_SMEM>>>(
            xh, wh + WK_OFF + (size_t)l * DDIM * DDIM, kh, MM, DDIM, DDIM,
            nullptr, 0, 1);

        attn_f16_kernel<<<BB * HH, 512, ATTN_SMEM>>>(kh, oh);

        // f = O @ Wo^T  -> fp32
        gemm_f16_kernel<<<dim3(DDIM / 128, MM / 128), 256, GEMM_SMEM>>>(
            oh, wh + WO_OFF + (size_t)l * DDIM * DDIM, f, MM, DDIM, DDIM,
            nullptr, 0, 0);

        // z = LN(f + x): exact fp32 + half copy
        ln_kernel<<<MM / 8, 256>>>(f, x, gamma + (size_t)l * DDIM,
                                   beta + (size_t)l * DDIM, z, zh);

        // hidden = relu(z @ W1 + b1) -> half
        gemm_f16_kernel<<<dim3(DFF / 128, MM / 128), 256, GEMM_SMEM>>>(
            zh, wh + W1_OFF + (size_t)l * DDIM * DFF, hh, MM, DFF, DDIM,
            b1 + (size_t)l * DFF, 1, 1);

        // f = hidden @ W2 + b2 -> fp32
        gemm_f16_kernel<<<dim3(DDIM / 128, MM / 128), 256, GEMM_SMEM>>>(
            hh, wh + W2_OFF + (size_t)l * DFF * DDIM, f, MM, DDIM, DFF,
            b2 + (size_t)l * DDIM, 0, 0);

        // x = LN(f + z): exact fp32 (+ half copy unless final)
        float* dstf = (l == LLAY - 1) ? (float*)d_out : x;
        __half* dsth = (l == LLAY - 1) ? (__half*)nullptr : xh;
        ln_kernel<<<MM / 8, 256>>>(f, z, gamma + (size_t)l * DDIM,
                                   beta + (size_t)l * DDIM, dstf, dsth);
    }
}

// round 14
// speedup vs baseline: 2.0602x; 1.0514x over previous
#include <cuda_runtime.h>
#include <cuda_fp16.h>
#include <cstddef>
#include <cstdint>

// Problem constants
#define BB   64
#define NN   300
#define DDIM 512
#define HH   8
#define DHD  64
#define LLAY 6
#define DFF  2048
#define MM   (BB*NN)   // 19200 rows

// ---------------- scratch (no allocation allowed) ----------------
__device__ float  g_x [MM*DDIM];          // exact residual x (fp32)
__device__ float  g_z [MM*DDIM];          // exact z (fp32)
__device__ float  g_f [MM*DDIM];          // fp32 GEMM outputs (Wo-out / FFN2-out)
__device__ __half g_xh[MM*DDIM];          // half copy of x (GEMM A)
__device__ __half g_zh[MM*DDIM];          // half copy of z (GEMM A)
__device__ __half g_kh[MM*DDIM];          // K-proj out (half, attn input)
__device__ __half g_oh[MM*DDIM];          // attn out (half, Wo GEMM A)
__device__ __half g_hh[(size_t)MM*DFF];   // FFN hidden (half)
// half weights, [N][K] transposed
#define WK_OFF 0
#define WO_OFF (LLAY*DDIM*DDIM)
#define W1_OFF (2*LLAY*DDIM*DDIM)
#define W2_OFF (2*LLAY*DDIM*DDIM + LLAY*DDIM*DFF)
__device__ __half g_w[2*LLAY*DDIM*DDIM + 2*LLAY*DDIM*DFF];

__device__ __forceinline__ void cp_async16(uint32_t smem_addr, const void* gptr) {
    asm volatile("cp.async.cg.shared.global [%0], [%1], 16;\n"
                 :: "r"(smem_addr), "l"(gptr));
}

#define MMA_F16(acc, a0,a1,a2,a3, b0,b1)                                    \
    asm volatile(                                                           \
        "mma.sync.aligned.m16n8k16.row.col.f32.f16.f16.f32 "                \
        "{%0,%1,%2,%3}, {%4,%5,%6,%7}, {%8,%9}, {%0,%1,%2,%3};"             \
        : "+f"(acc[0]), "+f"(acc[1]), "+f"(acc[2]), "+f"(acc[3])            \
        : "r"(a0), "r"(a1), "r"(a2), "r"(a3), "r"(b0), "r"(b1))

#define LDSM_X4(r0,r1,r2,r3, addr)                                          \
    asm volatile(                                                           \
        "ldmatrix.sync.aligned.m8n8.x4.shared.b16 {%0,%1,%2,%3}, [%4];"     \
        : "=r"(r0), "=r"(r1), "=r"(r2), "=r"(r3) : "r"(addr))

#define LDSM_X2_T(r0,r1, addr)                                              \
    asm volatile(                                                           \
        "ldmatrix.sync.aligned.m8n8.x2.trans.shared.b16 {%0,%1}, [%2];"     \
        : "=r"(r0), "=r"(r1) : "r"(addr))

// ---------------- embed: x = emb[tok] + pos -> fp32 + half ----------------
__global__ void embed_kernel(const int* __restrict__ tok,
                             const float* __restrict__ emb,
                             const float* __restrict__ pos,
                             float* __restrict__ x, __half* __restrict__ xh)
{
    int gid = blockIdx.x * blockDim.x + threadIdx.x;
    int row = gid >> 7;
    int c   = gid & 127;
    int t   = tok[row];
    int n   = row % NN;
    float4 e = ((const float4*)emb)[(size_t)t * 128 + c];
    float4 p = ((const float4*)pos)[(size_t)n * 128 + c];
    float4 v = make_float4(e.x + p.x, e.y + p.y, e.z + p.z, e.w + p.w);
    ((float4*)x)[gid] = v;
    __half2* xh2 = (__half2*)(xh + (size_t)gid * 4);
    xh2[0] = __floats2half2_rn(v.x, v.y);
    xh2[1] = __floats2half2_rn(v.z, v.w);
}

// ---------------- weight transpose to half: in [K][N] fp32 -> out [N][K] half ----------------
__global__ void half_transpose_kernel(const float* __restrict__ in,
                                      __half* __restrict__ out, int K, int N)
{
    __shared__ float t[32][33];
    const size_t loff = (size_t)blockIdx.z * K * N;
    const int k0 = blockIdx.y * 32;
    const int n0 = blockIdx.x * 32;
    const int tx = threadIdx.x, ty = threadIdx.y;   // 32 x 8
    #pragma unroll
    for (int i = 0; i < 32; i += 8)
        t[ty + i][tx] = in[loff + (size_t)(k0 + ty + i) * N + n0 + tx];
    __syncthreads();
    #pragma unroll
    for (int i = 0; i < 32; i += 8)
        out[loff + (size_t)(n0 + ty + i) * K + k0 + tx] =
            __float2half_rn(t[tx][ty + i]);
}

// Wk (L,H,D,DH): logical [K=D][N=H*DH] -> out [N][K] half per layer
__global__ void half_transpose_wk_kernel(const float* __restrict__ wk,
                                         __half* __restrict__ out)
{
    __shared__ float t[32][33];
    const int l  = blockIdx.z;
    const int k0 = blockIdx.y * 32;
    const int n0 = blockIdx.x * 32;
    const float* w = wk + (size_t)l * HH * DDIM * DHD;
    const int tx = threadIdx.x, ty = threadIdx.y;
    #pragma unroll
    for (int i = 0; i < 32; i += 8) {
        int k = k0 + ty + i, n = n0 + tx;
        t[ty + i][tx] = w[(size_t)(n >> 6) * (DDIM * DHD) + (size_t)k * DHD + (n & 63)];
    }
    __syncthreads();
    #pragma unroll
    for (int i = 0; i < 32; i += 8)
        out[(size_t)l * DDIM * DDIM + (size_t)(n0 + ty + i) * DDIM + k0 + tx] =
            __float2half_rn(t[tx][ty + i]);
}

// ---------------- fp16 tensor-core GEMM: C[M,N] = A @ BT^T ----------------
// A [M][K] half, BT [N][K] half. BM=BN=128, BK=64, 3-stage cp.async, 1 sync/ktile.
#define ALD      72                      // half stride (144B = 9 x 16B: conflict-free)
#define STG_H    (128*ALD)               // halves per (A or B) stage
#define STG_B    (STG_H*2)               // bytes
#define NSTG     3
#define GEMM_SMEM (2*NSTG*STG_B)         // 3 stages A + 3 stages B = 110592 B

__global__ __launch_bounds__(256)
void gemm_f16_kernel(const __half* __restrict__ A, const __half* __restrict__ BT,
                     void* __restrict__ Cv, int Mdim, int Ndim, int Kdim,
                     const float* __restrict__ bias, int relu, int outHalf)
{
    extern __shared__ __half hsm[];
    __half* Asm = hsm;                    // NSTG stages
    __half* Bsm = hsm + NSTG * STG_H;     // NSTG stages

    const int tid  = threadIdx.x;
    const int lane = tid & 31;
    const int w    = tid >> 5;
    const int g    = lane >> 2;
    const int tig  = lane & 3;

    const int warp_m = (w & 1) * 64;
    const int warp_n = (w >> 1) * 32;

    const int cRow = blockIdx.y * 128;
    const int cCol = blockIdx.x * 128;

    // copies: 128 rows x 8 pieces(16B) = 1024 pieces per matrix; 4 per thread
    const int r0 = tid >> 3;              // rows r0 + 32*j
    const int ci = tid & 7;               // 16B piece (8 halves)

    const __half* Ag = A  + (size_t)cRow * Kdim;
    const __half* Bg = BT + (size_t)cCol * Kdim;

    const uint32_t as_base = (uint32_t)__cvta_generic_to_shared(Asm);
    const uint32_t bs_base = (uint32_t)__cvta_generic_to_shared(Bsm);
    const uint32_t a_ld_off =
        ((uint32_t)(warp_m + (lane & 15)) * ALD + ((lane >> 4) << 3)) * 2;
    const uint32_t b_ld_off =
        ((uint32_t)(warp_n + ((lane >> 4) << 3) + (lane & 7)) * ALD
         + (((lane >> 3) & 1) << 3)) * 2;

    float acc[4][4][4];
    #pragma unroll
    for (int mi = 0; mi < 4; mi++)
        #pragma unroll
        for (int ni = 0; ni < 4; ni++)
            #pragma unroll
            for (int r = 0; r < 4; r++) acc[mi][ni][r] = 0.f;

    const int ktiles = Kdim >> 6;         // BK=64

    // prologue: tiles 0,1 -> stages 0,1
    #pragma unroll
    for (int s = 0; s < 2; s++) {
        const int kc = s << 6;
        #pragma unroll
        for (int j = 0; j < 4; j++) {
            int r = r0 + 32 * j;
            uint32_t so = (uint32_t)(s * STG_B) + (uint32_t)(r * ALD + ci * 8) * 2;
            cp_async16(as_base + so, Ag + (size_t)r * Kdim + kc + ci * 8);
            cp_async16(bs_base + so, Bg + (size_t)r * Kdim + kc + ci * 8);
        }
        asm volatile("cp.async.commit_group;\n");
    }

    for (int t = 0; t < ktiles; t++) {
        if (t + 1 < ktiles) {
            asm volatile("cp.async.wait_group 1;\n");
        } else {
            asm volatile("cp.async.wait_group 0;\n");
        }
        __syncthreads();   // single barrier per ktile

        const int buf = t % NSTG;
        const uint32_t a_stage = as_base + (uint32_t)(buf * STG_B) + a_ld_off;
        const uint32_t b_stage = bs_base + (uint32_t)(buf * STG_B) + b_ld_off;
        #pragma unroll
        for (int s = 0; s < 4; s++) {
            const uint32_t kofs = (uint32_t)s * 32;     // 16 halves
            uint32_t af[4][4];
            #pragma unroll
            for (int mi = 0; mi < 4; mi++)
                LDSM_X4(af[mi][0], af[mi][1], af[mi][2], af[mi][3],
                        a_stage + (uint32_t)(mi * 16 * ALD) * 2 + kofs);
            uint32_t bf[4][2];
            LDSM_X4(bf[0][0], bf[0][1], bf[1][0], bf[1][1], b_stage + kofs);
            LDSM_X4(bf[2][0], bf[2][1], bf[3][0], bf[3][1],
                    b_stage + (uint32_t)(16 * ALD) * 2 + kofs);
            #pragma unroll
            for (int mi = 0; mi < 4; mi++)
                #pragma unroll
                for (int ni = 0; ni < 4; ni++)
                    MMA_F16(acc[mi][ni], af[mi][0], af[mi][1], af[mi][2], af[mi][3],
                            bf[ni][0], bf[ni][1]);
        }

        // prefetch tile t+2 into stage (t+2)%3 — last read at iter t-1;
        // all warps passed sync(t), which requires compute(t-1) complete.
        if (t + 2 < ktiles) {
            const int sb = (t + 2) % NSTG;
            const int kc = (t + 2) << 6;
            #pragma unroll
            for (int j = 0; j < 4; j++) {
                int r = r0 + 32 * j;
                uint32_t so = (uint32_t)(sb * STG_B) + (uint32_t)(r * ALD + ci * 8) * 2;
                cp_async16(as_base + so, Ag + (size_t)r * Kdim + kc + ci * 8);
                cp_async16(bs_base + so, Bg + (size_t)r * Kdim + kc + ci * 8);
            }
            asm volatile("cp.async.commit_group;\n");
        }
    }

    // epilogue
    #pragma unroll
    for (int mi = 0; mi < 4; mi++) {
        int row0 = cRow + warp_m + mi * 16 + g;
        #pragma unroll
        for (int ni = 0; ni < 4; ni++) {
            int col = cCol + warp_n + ni * 8 + 2 * tig;
            float2 v0 = make_float2(acc[mi][ni][0], acc[mi][ni][1]);
            float2 v1 = make_float2(acc[mi][ni][2], acc[mi][ni][3]);
            if (bias) {
                float2 bb = *(const float2*)(bias + col);
                v0.x += bb.x; v0.y += bb.y;
                v1.x += bb.x; v1.y += bb.y;
            }
            if (relu) {
                v0.x = fmaxf(v0.x, 0.f); v0.y = fmaxf(v0.y, 0.f);
                v1.x = fmaxf(v1.x, 0.f); v1.y = fmaxf(v1.y, 0.f);
            }
            if (outHalf) {
                __half* Ch = (__half*)Cv;
                *(__half2*)(Ch + (size_t)row0       * Ndim + col) =
                    __floats2half2_rn(v0.x, v0.y);
                *(__half2*)(Ch + (size_t)(row0 + 8) * Ndim + col) =
                    __floats2half2_rn(v1.x, v1.y);
            } else {
                float* Cf = (float*)Cv;
                *(float2*)(Cf + (size_t)row0       * Ndim + col) = v0;
                *(float2*)(Cf + (size_t)(row0 + 8) * Ndim + col) = v1;
            }
        }
    }
}

// ---------------- fp16 tensor-core attention ----------------
// K tile [320][72] half; scores/probs [64][312] half. 512 threads, 16 warps.
#define KPAD   320
#define KLD2   72
#define PSLD   312
#define MQ     64
#define NKEY   304              // 19 k16 steps in O-phase
#define ATTN_SMEM ((KPAD*KLD2 + MQ*PSLD) * 2)

__global__ __launch_bounds__(512)
void attn_f16_kernel(const __half* __restrict__ k, __half* __restrict__ o)
{
    extern __shared__ __half smh[];
    __half* Ks = smh;                       // KPAD x KLD2
    __half* Ps = smh + KPAD * KLD2;         // MQ x PSLD

    const int bh = blockIdx.x;
    const int b  = bh / HH, h = bh % HH;
    const __half* kbase = k + (size_t)b * NN * DDIM + h * DHD;

    const int tid  = threadIdx.x;
    const int lane = tid & 31;
    const int w    = tid >> 5;      // 0..15
    const int g    = lane >> 2;
    const int tig  = lane & 3;

    const uint32_t ks_addr = (uint32_t)__cvta_generic_to_shared(Ks);
    const uint32_t ps_addr = (uint32_t)__cvta_generic_to_shared(Ps);

    // load K head tile (zero-pad rows >= NN); cols 64..71 never read
    for (int i = tid; i < KPAD * DHD; i += 512) {
        int m = i >> 6, e = i & 63;
        Ks[m * KLD2 + e] = (m < NN) ? kbase[(size_t)m * DDIM + e] : __half(0.f);
    }
    __syncthreads();

    const float scale = 0.04419417382415922f;   // 1/sqrt(512)
    const int mi  = w & 3;        // q m-tile
    const int qtr = w >> 2;       // key/channel quarter

    const uint32_t a_row  = (uint32_t)(lane & 15);
    const uint32_t a_coff = (uint32_t)((lane >> 4) << 3);    // halves
    const uint32_t bp_row = (uint32_t)(((lane >> 4) << 3) + (lane & 7));
    const uint32_t bp_cof = (uint32_t)(((lane >> 3) & 1) << 3);

    for (int it = 0; it < 5; it++) {
        const int q0 = it * MQ;

        // ---- S = Q K^T : 10 n8-tiles per warp, 4 k16 steps ----
        {
            float acc[10][4];
            #pragma unroll
            for (int ni = 0; ni < 10; ni++)
                #pragma unroll
                for (int r = 0; r < 4; r++) acc[ni][r] = 0.f;

            const uint32_t a_base = ks_addr +
                ((q0 + mi * 16 + a_row) * KLD2 + a_coff) * 2;
            const uint32_t b_base = ks_addr +
                ((qtr * 80 + bp_row) * KLD2 + bp_cof) * 2;

            #pragma unroll
            for (int s = 0; s < 4; s++) {
                const uint32_t kofs = (uint32_t)s * 32;   // 16 halves
                uint32_t a0, a1, a2, a3;
                LDSM_X4(a0, a1, a2, a3, a_base + kofs);
                #pragma unroll
                for (int p = 0; p < 5; p++) {
                    uint32_t b0, b1, b2, b3;
                    LDSM_X4(b0, b1, b2, b3,
                            b_base + (uint32_t)(p * 16 * KLD2) * 2 + kofs);
                    MMA_F16(acc[2*p    ], a0, a1, a2, a3, b0, b1);
                    MMA_F16(acc[2*p + 1], a0, a1, a2, a3, b2, b3);
                }
            }
            const int row0 = mi * 16 + g;
            #pragma unroll
            for (int ni = 0; ni < 10; ni++) {
                int col = qtr * 80 + ni * 8 + 2 * tig;
                if (col < NKEY) {
                    float s0 = (col     < NN) ? acc[ni][0] * scale : -60000.f;
                    float s1 = (col + 1 < NN) ? acc[ni][1] * scale : -60000.f;
                    float s2 = (col     < NN) ? acc[ni][2] * scale : -60000.f;
                    float s3 = (col + 1 < NN) ? acc[ni][3] * scale : -60000.f;
                    *(__half2*)(Ps + row0 * PSLD + col) = __floats2half2_rn(s0, s1);
                    *(__half2*)(Ps + (row0 + 8) * PSLD + col) = __floats2half2_rn(s2, s3);
                }
            }
        }
        __syncthreads();

        // ---- softmax: warp w -> rows [4w, 4w+4), 304 cols ----
        #pragma unroll
        for (int r = 0; r < 4; r++) {
            const int row = w * 4 + r;
            __half* prow = Ps + row * PSLD;
            float v[10];
            float mx = -1e30f;
            #pragma unroll
            for (int j = 0; j < 10; j++) {
                int c = lane + 32 * j;
                float s = (c < NKEY) ? __half2float(prow[c]) : -60000.f;
                v[j] = s;
                mx = fmaxf(mx, s);
            }
            #pragma unroll
            for (int off = 16; off; off >>= 1)
                mx = fmaxf(mx, __shfl_xor_sync(0xffffffffu, mx, off));
            float sum = 0.f;
            #pragma unroll
            for (int j = 0; j < 10; j++) {
                float ev = __expf(v[j] - mx);
                v[j] = ev;
                sum += ev;
            }
            #pragma unroll
            for (int off = 16; off; off >>= 1)
                sum += __shfl_xor_sync(0xffffffffu, sum, off);
            float inv = 1.f / sum;
            #pragma unroll
            for (int j = 0; j < 10; j++) {
                int c = lane + 32 * j;
                if (c < NKEY) prow[c] = __float2half_rn(v[j] * inv);
            }
        }
        __syncthreads();

        // ---- O = P K : 2 n8-tiles (16 channels) per warp, 19 k16 steps ----
        {
            float oacc[2][4];
            #pragma unroll
            for (int ni = 0; ni < 2; ni++)
                #pragma unroll
                for (int r = 0; r < 4; r++) oacc[ni][r] = 0.f;

            const uint32_t pa_base = ps_addr + ((mi * 16 + a_row) * PSLD + a_coff) * 2;
            const int ch0 = qtr * 16;
            const uint32_t kb_base = ks_addr + ((uint32_t)(lane & 15) * KLD2) * 2;

            #pragma unroll 1
            for (int s = 0; s < 19; s++) {
                const int kk = s * 16;
                uint32_t a0, a1, a2, a3;
                LDSM_X4(a0, a1, a2, a3, pa_base + (uint32_t)(kk) * 2);
                uint32_t b00, b01, b10, b11;
                LDSM_X2_T(b00, b01,
                          kb_base + ((uint32_t)(kk * KLD2) + ch0) * 2);
                LDSM_X2_T(b10, b11,
                          kb_base + ((uint32_t)(kk * KLD2) + ch0 + 8) * 2);
                MMA_F16(oacc[0], a0, a1, a2, a3, b00, b01);
                MMA_F16(oacc[1], a0, a1, a2, a3, b10, b11);
            }
            const int q = q0 + mi * 16 + g;
            __half* ob = o + (size_t)b * NN * DDIM + h * DHD;
            #pragma unroll
            for (int ni = 0; ni < 2; ni++) {
                int ch = ch0 + ni * 8 + 2 * tig;
                if (q < NN)
                    *(__half2*)(ob + (size_t)q * DDIM + ch) =
                        __floats2half2_rn(oacc[ni][0], oacc[ni][1]);
                if (q + 8 < NN)
                    *(__half2*)(ob + (size_t)(q + 8) * DDIM + ch) =
                        __floats2half2_rn(oacc[ni][2], oacc[ni][3]);
            }
        }
        __syncthreads();
    }
}

// ---------------- residual + LayerNorm: fp32 out (opt) + half out (opt) ----------------
__global__ __launch_bounds__(256)
void ln_kernel(const float* __restrict__ a, const float* __restrict__ b,
               const float* __restrict__ gamma, const float* __restrict__ beta,
               float* __restrict__ outf, __half* __restrict__ outh)
{
    int w    = threadIdx.x >> 5;
    int lane = threadIdx.x & 31;
    int row  = blockIdx.x * 8 + w;

    const float4* a4 = (const float4*)(a + (size_t)row * DDIM);
    const float4* b4 = (const float4*)(b + (size_t)row * DDIM);
    float4 v[4];
    float s1 = 0.f, s2 = 0.f;
    #pragma unroll
    for (int j = 0; j < 4; j++) {
        float4 av = a4[j * 32 + lane];
        float4 bv = b4[j * 32 + lane];
        float4 t = make_float4(av.x + bv.x, av.y + bv.y, av.z + bv.z, av.w + bv.w);
        v[j] = t;
        s1 += t.x + t.y + t.z + t.w;
        s2 += t.x * t.x + t.y * t.y + t.z * t.z + t.w * t.w;
    }
    #pragma unroll
    for (int off = 16; off; off >>= 1) {
        s1 += __shfl_xor_sync(0xffffffffu, s1, off);
        s2 += __shfl_xor_sync(0xffffffffu, s2, off);
    }
    float mean = s1 * (1.f / DDIM);
    float var  = s2 * (1.f / DDIM) - mean * mean;
    float rs   = rsqrtf(var + 1e-5f);

    const float4* g4  = (const float4*)gamma;
    const float4* be4 = (const float4*)beta;
    #pragma unroll
    for (int j = 0; j < 4; j++) {
        float4 g = g4[j * 32 + lane];
        float4 be = be4[j * 32 + lane];
        float4 t = v[j];
        float4 r;
        r.x = (t.x - mean) * rs * g.x + be.x;
        r.y = (t.y - mean) * rs * g.y + be.y;
        r.z = (t.z - mean) * rs * g.z + be.z;
        r.w = (t.w - mean) * rs * g.w + be.w;
        if (outf)
            ((float4*)(outf + (size_t)row * DDIM))[j * 32 + lane] = r;
        if (outh) {
            __half2* o2 = (__half2*)(outh + (size_t)row * DDIM) + (j * 32 + lane) * 2;
            o2[0] = __floats2half2_rn(r.x, r.y);
            o2[1] = __floats2half2_rn(r.z, r.w);
        }
    }
}

// ---------------- launcher ----------------
extern "C" void kernel_launch(void* const* d_in, const int* in_sizes, int n_in,
                              void* d_out, int out_size)
{
    const int*   tokens = (const int*)  d_in[0];
    const float* emb    = (const float*)d_in[1];
    const float* pos    = (const float*)d_in[2];
    const float* Wk     = (const float*)d_in[3];
    const float* Wo     = (const float*)d_in[4];
    const float* W1     = (const float*)d_in[5];
    const float* b1     = (const float*)d_in[6];
    const float* W2     = (const float*)d_in[7];
    const float* b2     = (const float*)d_in[8];
    const float* gamma  = (const float*)d_in[9];
    const float* beta   = (const float*)d_in[10];

    float *x, *z, *f;
    __half *xh, *zh, *kh, *oh, *hh, *wh;
    cudaGetSymbolAddress((void**)&x,  g_x);
    cudaGetSymbolAddress((void**)&z,  g_z);
    cudaGetSymbolAddress((void**)&f,  g_f);
    cudaGetSymbolAddress((void**)&xh, g_xh);
    cudaGetSymbolAddress((void**)&zh, g_zh);
    cudaGetSymbolAddress((void**)&kh, g_kh);
    cudaGetSymbolAddress((void**)&oh, g_oh);
    cudaGetSymbolAddress((void**)&hh, g_hh);
    cudaGetSymbolAddress((void**)&wh, g_w);

    cudaFuncSetAttribute(attn_f16_kernel,
                         cudaFuncAttributeMaxDynamicSharedMemorySize, ATTN_SMEM);
    cudaFuncSetAttribute(gemm_f16_kernel,
                         cudaFuncAttributeMaxDynamicSharedMemorySize, GEMM_SMEM);

    dim3 tb(32, 8);
    half_transpose_wk_kernel<<<dim3(DDIM/32, DDIM/32, LLAY), tb>>>(Wk, wh + WK_OFF);
    half_transpose_kernel<<<dim3(DDIM/32, DDIM/32, LLAY), tb>>>(Wo, wh + WO_OFF, DDIM, DDIM);
    half_transpose_kernel<<<dim3(DFF/32, DDIM/32, LLAY), tb>>>(W1, wh + W1_OFF, DDIM, DFF);
    half_transpose_kernel<<<dim3(DDIM/32, DFF/32, LLAY), tb>>>(W2, wh + W2_OFF, DFF, DDIM);

    embed_kernel<<<(MM * 128) / 256, 256>>>(tokens, emb, pos, x, xh);

    for (int l = 0; l < LLAY; l++) {
        // K = X @ Wk[l]^T  -> half
        gemm_f16_kernel<<<dim3(DDIM / 128, MM / 128), 256, GEMM_SMEM>>>(
            xh, wh + WK_OFF + (size_t)l * DDIM * DDIM, kh, MM, DDIM, DDIM,
            nullptr, 0, 1);

        attn_f16_kernel<<<BB * HH, 512, ATTN_SMEM>>>(kh, oh);

        // f = O @ Wo^T  -> fp32
        gemm_f16_kernel<<<dim3(DDIM / 128, MM / 128), 256, GEMM_SMEM>>>(
            oh, wh + WO_OFF + (size_t)l * DDIM * DDIM, f, MM, DDIM, DDIM,
            nullptr, 0, 0);

        // z = LN(f + x): exact fp32 + half copy
        ln_kernel<<<MM / 8, 256>>>(f, x, gamma + (size_t)l * DDIM,
                                   beta + (size_t)l * DDIM, z, zh);

        // hidden = relu(z @ W1 + b1) -> half
        gemm_f16_kernel<<<dim3(DFF / 128, MM / 128), 256, GEMM_SMEM>>>(
            zh, wh + W1_OFF + (size_t)l * DDIM * DFF, hh, MM, DFF, DDIM,
            b1 + (size_t)l * DFF, 1, 1);

        // f = hidden @ W2 + b2 -> fp32
        gemm_f16_kernel<<<dim3(DDIM / 128, MM / 128), 256, GEMM_SMEM>>>(
            hh, wh + W2_OFF + (size_t)l * DFF * DDIM, f, MM, DDIM, DFF,
            b2 + (size_t)l * DDIM, 0, 0);

        // x = LN(f + z): exact fp32 (+ half copy unless final)
        float* dstf = (l == LLAY - 1) ? (float*)d_out : x;
        __half* dsth = (l == LLAY - 1) ? (__half*)nullptr : xh;
        ln_kernel<<<MM / 8, 256>>>(f, z, gamma + (size_t)l * DDIM,
                                   beta + (size_t)l * DDIM, dstf, dsth);
    }
}